// round 1
// baseline (speedup 1.0000x reference)
#include <cuda_runtime.h>
#include <math.h>

#define BB 64
#define CC 1024
#define CQ 256
#define MI 128
#define HW 256

// ---------------- scratch (device globals; no allocation allowed) ----------------
__device__ __align__(256) float g_xsum[BB*CC*HW];    // x_sum
__device__ __align__(256) float g_feat[BB*CC*HW];    // feature (stage 2/3 input)
__device__ __align__(256) float g_f   [BB*CQ*HW];    // current f_i  [b][c][hw]
__device__ __align__(256) float g_ft  [BB*HW*CQ];    // f transposed [b][i][c]
__device__ __align__(256) float g_wf  [9*CC*CQ];     // fused conv weights [t][c][o]
__device__ __align__(256) float g_bf  [CQ];
__device__ __align__(256) float g_k   [BB*MI*HW];    // relu(k) [b][m][i]
__device__ __align__(256) float g_cw  [BB*MI];
__device__ __align__(256) float g_scw [BB*MI];       // sqrt(cw)
__device__ __align__(256) float g_avg [BB*CQ];
__device__ __align__(256) float g_mx  [BB*CQ];
__device__ __align__(256) float g_rs  [BB*HW];       // row sums of sigmoid(A)
__device__ __align__(256) float g_dinv[BB*HW];       // rs^-0.5
__device__ __align__(256) float g_z   [BB*MI*CQ];    // cw ⊙ PtX
__device__ __align__(256) float g_lx  [BB*HW*CQ];    // LX [b][i][c]
__device__ __align__(256) float g_x123[BB*3*CQ*HW];  // concat(x1,x2,x3) [b][c][hw]

// ---------------- upsample (align_corners) + fuse: x_sum = x_cur*(up+1) ----------
__global__ void k_upsample_fuse(const float* __restrict__ xc, const float* __restrict__ xl) {
    int idx = blockIdx.x * 256 + threadIdx.x;
    if (idx >= BB*CC*HW) return;
    int hw = idx & 255; int bc = idx >> 8;
    int y = hw >> 4, x = hw & 15;
    float ys = y * (7.0f / 15.0f);
    float xs = x * (7.0f / 15.0f);
    int y0 = (int)floorf(ys), x0 = (int)floorf(xs);
    int y1 = min(y0 + 1, 7), x1 = min(x0 + 1, 7);
    float wy = ys - (float)y0, wx = xs - (float)x0;
    const float* base = xl + (size_t)bc * 64;
    float v00 = base[y0*8+x0], v01 = base[y0*8+x1];
    float v10 = base[y1*8+x0], v11 = base[y1*8+x1];
    float top = v00*(1.f-wx) + v01*wx;
    float bot = v10*(1.f-wx) + v11*wx;
    float up  = top*(1.f-wy) + bot*wy;
    g_xsum[idx] = xc[idx] * (up + 1.0f);
}

// ------------- fold 1x1 into center tap of 3x3; layout wf[t][c][o] ---------------
__global__ void k_fuse_weights(const float* __restrict__ rw, const float* __restrict__ rb,
                               const float* __restrict__ cw, const float* __restrict__ cb) {
    int idx = blockIdx.x * 256 + threadIdx.x;   // over 9*1024*256
    if (idx >= 9*CC*CQ) return;
    int o = idx & 255; int tc = idx >> 8;
    int c = tc & 1023; int t = tc >> 10;
    float v = rw[((size_t)o*CC + c)*9 + t];
    if (t == 4) v += cw[(size_t)o*CC + c];
    g_wf[idx] = v;
    if (idx < CQ) g_bf[idx] = rb[idx] + cb[idx];
}

// ------------- dilated conv3x3 (fused 1x1): f = conv(in) + bf --------------------
// grid (256 n-tiles, 4 m-tiles), 256 threads, 64x64x16 tile, 4x4 micro
__global__ void k_conv3x3(const float* __restrict__ in, int dil) {
    __shared__ float Ws[16][64];
    __shared__ float Is[16][64];
    int tid = threadIdx.x;
    int ty = tid >> 4, tx = tid & 15;
    int n0 = blockIdx.x * 64;
    int b = n0 >> 8, hw0 = n0 & 255;
    int m0 = blockIdx.y * 64;
    float acc[4][4] = {};
    const float* inb = in + (size_t)b * CC * HW;
    for (int t = 0; t < 9; t++) {
        int dy = dil * ((t / 3) - 1);
        int dx = dil * ((t % 3) - 1);
        for (int ck = 0; ck < CC; ck += 16) {
            #pragma unroll
            for (int r = 0; r < 4; r++) {
                int idx = tid + 256 * r;
                int kk = idx >> 6, col = idx & 63;
                Ws[kk][col] = g_wf[((size_t)t*CC + ck + kk)*CQ + m0 + col];
                int hw = hw0 + col;
                int y = (hw >> 4) + dy, x = (hw & 15) + dx;
                float v = 0.f;
                if ((unsigned)y < 16u && (unsigned)x < 16u)
                    v = inb[(size_t)(ck + kk)*HW + y*16 + x];
                Is[kk][col] = v;
            }
            __syncthreads();
            #pragma unroll
            for (int kk = 0; kk < 16; kk++) {
                float av[4], bv[4];
                #pragma unroll
                for (int u = 0; u < 4; u++) av[u] = Ws[kk][ty + 16*u];
                #pragma unroll
                for (int v = 0; v < 4; v++) bv[v] = Is[kk][tx + 16*v];
                #pragma unroll
                for (int u = 0; u < 4; u++)
                    #pragma unroll
                    for (int v = 0; v < 4; v++)
                        acc[u][v] += av[u] * bv[v];
            }
            __syncthreads();
        }
    }
    #pragma unroll
    for (int u = 0; u < 4; u++) {
        int o = m0 + ty + 16*u;
        float bias = g_bf[o];
        #pragma unroll
        for (int v = 0; v < 4; v++) {
            int hw = hw0 + tx + 16*v;
            g_f[((size_t)b*CQ + o)*HW + hw] = acc[u][v] + bias;
        }
    }
}

// ------------- generic 1x1 GEMM over NCHW: out = [relu](W @ in + bias [+ add]) ---
__global__ void k_gemm(const float* __restrict__ in, const float* __restrict__ Wt,
                       const float* __restrict__ bias, const float* __restrict__ add,
                       float* __restrict__ out, int Ci, int Co, int relu) {
    __shared__ float Ws[16][64];
    __shared__ float Is[16][64];
    int tid = threadIdx.x;
    int ty = tid >> 4, tx = tid & 15;
    int n0 = blockIdx.x * 64;
    int b = n0 >> 8, hw0 = n0 & 255;
    int m0 = blockIdx.y * 64;
    float acc[4][4] = {};
    const float* inb = in + (size_t)b * Ci * HW;
    for (int ck = 0; ck < Ci; ck += 16) {
        {   // weight tile via float4 (Ci multiple of 4, offsets 16-aligned)
            int mm = tid >> 2, k4 = (tid & 3) * 4;
            float4 w4 = *(const float4*)&Wt[(size_t)(m0 + mm)*Ci + ck + k4];
            Ws[k4+0][mm] = w4.x; Ws[k4+1][mm] = w4.y;
            Ws[k4+2][mm] = w4.z; Ws[k4+3][mm] = w4.w;
        }
        #pragma unroll
        for (int r = 0; r < 4; r++) {
            int idx = tid + 256 * r;
            int kk = idx >> 6, nn = idx & 63;
            Is[kk][nn] = inb[(size_t)(ck + kk)*HW + hw0 + nn];
        }
        __syncthreads();
        #pragma unroll
        for (int kk = 0; kk < 16; kk++) {
            float av[4], bv[4];
            #pragma unroll
            for (int u = 0; u < 4; u++) av[u] = Ws[kk][ty + 16*u];
            #pragma unroll
            for (int v = 0; v < 4; v++) bv[v] = Is[kk][tx + 16*v];
            #pragma unroll
            for (int u = 0; u < 4; u++)
                #pragma unroll
                for (int v = 0; v < 4; v++)
                    acc[u][v] += av[u] * bv[v];
        }
        __syncthreads();
    }
    #pragma unroll
    for (int u = 0; u < 4; u++) {
        int o = m0 + ty + 16*u;
        float bi = bias[o];
        #pragma unroll
        for (int v = 0; v < 4; v++) {
            int hw = hw0 + tx + 16*v;
            float vv = acc[u][v] + bi;
            if (relu) vv = fmaxf(vv, 0.f);
            size_t oi = ((size_t)b*Co + o)*HW + hw;
            if (add) vv += add[oi];
            out[oi] = vv;
        }
    }
}

// ------------- per-(b,c) spatial mean/max over HW=256 (one warp each) ------------
__global__ void k_avgmax() {
    int gw = (blockIdx.x * blockDim.x + threadIdx.x) >> 5;
    int lane = threadIdx.x & 31;
    if (gw >= BB*CQ) return;
    const float* p = g_f + (size_t)gw * HW;
    float s = 0.f, m = -INFINITY;
    for (int i = lane; i < HW; i += 32) { float v = p[i]; s += v; m = fmaxf(m, v); }
    #pragma unroll
    for (int off = 16; off; off >>= 1) {
        s += __shfl_down_sync(0xffffffffu, s, off);
        m  = fmaxf(m, __shfl_down_sync(0xffffffffu, m, off));
    }
    if (lane == 0) { g_avg[gw] = s * (1.0f/256.0f); g_mx[gw] = m; }
}

// ------------- cw = sigmoid(relu(avg@avg_w^T) + relu(mx@max_w^T)) ----------------
__global__ void k_cw(const float* __restrict__ aw, const float* __restrict__ mw) {
    __shared__ float sa[CQ], sm[CQ];
    int b = blockIdx.x, m = threadIdx.x;
    for (int i = m; i < CQ; i += 128) {
        sa[i] = g_avg[b*CQ + i];
        sm[i] = g_mx [b*CQ + i];
    }
    __syncthreads();
    float s1 = 0.f, s2 = 0.f;
    for (int c = 0; c < CQ; c++) {
        s1 += sa[c] * aw[m*CQ + c];
        s2 += sm[c] * mw[m*CQ + c];
    }
    float val = fmaxf(s1, 0.f) + fmaxf(s2, 0.f);
    float cwv = 1.0f / (1.0f + expf(-val));
    g_cw [b*MI + m] = cwv;
    g_scw[b*MI + m] = sqrtf(cwv);
}

__global__ void k_zero_rs() {
    int idx = blockIdx.x * 256 + threadIdx.x;
    if (idx < BB*HW) g_rs[idx] = 0.f;
}

// ------------- row-sums of sigmoid(G^T G), G[m,i] = sqrt(cw[m])*k[m,i] -----------
// grid (4 j-tiles, 4 i-tiles, 64 batches)
__global__ void k_Arowsum() {
    __shared__ float Gi[16][64];
    __shared__ float Gj[16][64];
    __shared__ float rsum[64];
    int tid = threadIdx.x;
    int ty = tid >> 4, tx = tid & 15;
    int b = blockIdx.z;
    int i0 = blockIdx.y * 64, j0 = blockIdx.x * 64;
    if (tid < 64) rsum[tid] = 0.f;
    float acc[4][4] = {};
    for (int mk = 0; mk < MI; mk += 16) {
        #pragma unroll
        for (int r = 0; r < 4; r++) {
            int idx = tid + 256 * r;
            int kk = idx >> 6, col = idx & 63;
            float sc = g_scw[b*MI + mk + kk];
            const float* krow = g_k + ((size_t)b*MI + mk + kk)*HW;
            Gi[kk][col] = krow[i0 + col] * sc;
            Gj[kk][col] = krow[j0 + col] * sc;
        }
        __syncthreads();
        #pragma unroll
        for (int kk = 0; kk < 16; kk++) {
            float av[4], bv[4];
            #pragma unroll
            for (int u = 0; u < 4; u++) av[u] = Gi[kk][ty + 16*u];
            #pragma unroll
            for (int v = 0; v < 4; v++) bv[v] = Gj[kk][tx + 16*v];
            #pragma unroll
            for (int u = 0; u < 4; u++)
                #pragma unroll
                for (int v = 0; v < 4; v++)
                    acc[u][v] += av[u] * bv[v];
        }
        __syncthreads();
    }
    #pragma unroll
    for (int u = 0; u < 4; u++) {
        float part = 0.f;
        #pragma unroll
        for (int v = 0; v < 4; v++)
            part += 1.0f / (1.0f + expf(-acc[u][v]));
        atomicAdd(&rsum[ty + 16*u], part);
    }
    __syncthreads();
    if (tid < 64) atomicAdd(&g_rs[b*HW + i0 + tid], rsum[tid]);
}

__global__ void k_dinv() {
    int idx = blockIdx.x * 256 + threadIdx.x;
    if (idx < BB*HW) g_dinv[idx] = rsqrtf(g_rs[idx]);
}

// ------------- transpose f[b][c][i] -> ft[b][i][c] -------------------------------
__global__ void k_transpose() {
    __shared__ float t[32][33];
    int b = blockIdx.z;
    int c0 = blockIdx.x * 32, i0 = blockIdx.y * 32;
    for (int j = threadIdx.y; j < 32; j += 8)
        t[j][threadIdx.x] = g_f[((size_t)b*CQ + c0 + j)*HW + i0 + threadIdx.x];
    __syncthreads();
    for (int j = threadIdx.y; j < 32; j += 8)
        g_ft[((size_t)b*HW + i0 + j)*CQ + c0 + threadIdx.x] = t[threadIdx.x][j];
}

// ------------- Z[m,c] = cw[m] * sum_i d[i]*k[m,i]*ft[i,c] ------------------------
// grid (4 c-tiles, 2 m-tiles, 64)
__global__ void k_ptz() {
    __shared__ float As[16][64];
    __shared__ float Bs[16][64];
    int tid = threadIdx.x;
    int ty = tid >> 4, tx = tid & 15;
    int b = blockIdx.z;
    int m0 = blockIdx.y * 64, c0 = blockIdx.x * 64;
    float acc[4][4] = {};
    for (int ik = 0; ik < HW; ik += 16) {
        {
            int mm = tid >> 2, k4 = (tid & 3) * 4;
            const float* krow = g_k + ((size_t)b*MI + m0 + mm)*HW + ik + k4;
            float4 k4v = *(const float4*)krow;
            const float* dv = g_dinv + b*HW + ik + k4;
            As[k4+0][mm] = k4v.x * dv[0];
            As[k4+1][mm] = k4v.y * dv[1];
            As[k4+2][mm] = k4v.z * dv[2];
            As[k4+3][mm] = k4v.w * dv[3];
        }
        #pragma unroll
        for (int r = 0; r < 4; r++) {
            int idx = tid + 256 * r;
            int kk = idx >> 6, nn = idx & 63;
            Bs[kk][nn] = g_ft[((size_t)b*HW + ik + kk)*CQ + c0 + nn];
        }
        __syncthreads();
        #pragma unroll
        for (int kk = 0; kk < 16; kk++) {
            float av[4], bv[4];
            #pragma unroll
            for (int u = 0; u < 4; u++) av[u] = As[kk][ty + 16*u];
            #pragma unroll
            for (int v = 0; v < 4; v++) bv[v] = Bs[kk][tx + 16*v];
            #pragma unroll
            for (int u = 0; u < 4; u++)
                #pragma unroll
                for (int v = 0; v < 4; v++)
                    acc[u][v] += av[u] * bv[v];
        }
        __syncthreads();
    }
    #pragma unroll
    for (int u = 0; u < 4; u++) {
        int m = m0 + ty + 16*u;
        float cwm = g_cw[b*MI + m];
        #pragma unroll
        for (int v = 0; v < 4; v++)
            g_z[((size_t)b*MI + m)*CQ + c0 + tx + 16*v] = acc[u][v] * cwm;
    }
}

// ------------- LX[i,c] = ft[i,c] - d[i]*sum_m k[m,i]*Z[m,c] ----------------------
// grid (4 c-tiles, 4 i-tiles, 64)
__global__ void k_lx() {
    __shared__ float As[16][64];
    __shared__ float Bs[16][64];
    int tid = threadIdx.x;
    int ty = tid >> 4, tx = tid & 15;
    int b = blockIdx.z;
    int i0 = blockIdx.y * 64, c0 = blockIdx.x * 64;
    float acc[4][4] = {};
    for (int mk = 0; mk < MI; mk += 16) {
        #pragma unroll
        for (int r = 0; r < 4; r++) {
            int idx = tid + 256 * r;
            int kk = idx >> 6, col = idx & 63;
            As[kk][col] = g_k[((size_t)b*MI + mk + kk)*HW + i0 + col];
            Bs[kk][col] = g_z[((size_t)b*MI + mk + kk)*CQ + c0 + col];
        }
        __syncthreads();
        #pragma unroll
        for (int kk = 0; kk < 16; kk++) {
            float av[4], bv[4];
            #pragma unroll
            for (int u = 0; u < 4; u++) av[u] = As[kk][ty + 16*u];
            #pragma unroll
            for (int v = 0; v < 4; v++) bv[v] = Bs[kk][tx + 16*v];
            #pragma unroll
            for (int u = 0; u < 4; u++)
                #pragma unroll
                for (int v = 0; v < 4; v++)
                    acc[u][v] += av[u] * bv[v];
        }
        __syncthreads();
    }
    #pragma unroll
    for (int u = 0; u < 4; u++) {
        int i = i0 + ty + 16*u;
        float di = g_dinv[b*HW + i];
        #pragma unroll
        for (int v = 0; v < 4; v++) {
            size_t oi = ((size_t)b*HW + i)*CQ + c0 + tx + 16*v;
            g_lx[oi] = g_ft[oi] - di * acc[u][v];
        }
    }
}

// ------------- Y = ft + LX @ gcn_w ; store transposed into x123 ------------------
// grid (4 c-tiles, 4 i-tiles, 64)
__global__ void k_y(const float* __restrict__ gcn, int soff) {
    __shared__ float As[16][64];
    __shared__ float Bs[16][64];
    int tid = threadIdx.x;
    int ty = tid >> 4, tx = tid & 15;
    int b = blockIdx.z;
    int i0 = blockIdx.y * 64, c0 = blockIdx.x * 64;
    float acc[4][4] = {};
    for (int ck = 0; ck < CQ; ck += 16) {
        {
            int mm = tid >> 2, k4 = (tid & 3) * 4;
            float4 a4 = *(const float4*)&g_lx[((size_t)b*HW + i0 + mm)*CQ + ck + k4];
            As[k4+0][mm] = a4.x; As[k4+1][mm] = a4.y;
            As[k4+2][mm] = a4.z; As[k4+3][mm] = a4.w;
        }
        #pragma unroll
        for (int r = 0; r < 4; r++) {
            int idx = tid + 256 * r;
            int kk = idx >> 6, nn = idx & 63;
            Bs[kk][nn] = gcn[(size_t)(ck + kk)*CQ + c0 + nn];
        }
        __syncthreads();
        #pragma unroll
        for (int kk = 0; kk < 16; kk++) {
            float av[4], bv[4];
            #pragma unroll
            for (int u = 0; u < 4; u++) av[u] = As[kk][ty + 16*u];
            #pragma unroll
            for (int v = 0; v < 4; v++) bv[v] = Bs[kk][tx + 16*v];
            #pragma unroll
            for (int u = 0; u < 4; u++)
                #pragma unroll
                for (int v = 0; v < 4; v++)
                    acc[u][v] += av[u] * bv[v];
        }
        __syncthreads();
    }
    #pragma unroll
    for (int u = 0; u < 4; u++) {
        int i = i0 + ty + 16*u;
        #pragma unroll
        for (int v = 0; v < 4; v++) {
            int c = c0 + tx + 16*v;
            float val = g_ft[((size_t)b*HW + i)*CQ + c] + acc[u][v];
            g_x123[((size_t)b*(3*CQ) + soff + c)*HW + i] = val;
        }
    }
}

// ---------------------------------------------------------------------------------
extern "C" void kernel_launch(void* const* d_in, const int* in_sizes, int n_in,
                              void* d_out, int out_size) {
    (void)in_sizes; (void)n_in; (void)out_size;
    const float* x_cur  = (const float*)d_in[0];
    const float* x_lat  = (const float*)d_in[1];
    const float* conv_w = (const float*)d_in[2];
    const float* conv_b = (const float*)d_in[3];
    const float* conv1_w= (const float*)d_in[4];
    const float* conv1_b= (const float*)d_in[5];
    const float* conv3_w= (const float*)d_in[6];
    const float* conv3_b= (const float*)d_in[7];
    const float* rw[3]  = {(const float*)d_in[8], (const float*)d_in[10], (const float*)d_in[12]};
    const float* rb[3]  = {(const float*)d_in[9], (const float*)d_in[11], (const float*)d_in[13]};
    const float* ck_w   = (const float*)d_in[14];
    const float* ck_b   = (const float*)d_in[15];
    const float* avg_w  = (const float*)d_in[16];
    const float* max_w  = (const float*)d_in[17];
    const float* gcn_w  = (const float*)d_in[18];
    float* out = (float*)d_out;

    float *p_xsum, *p_feat, *p_f, *p_k, *p_x123;
    cudaGetSymbolAddress((void**)&p_xsum, g_xsum);
    cudaGetSymbolAddress((void**)&p_feat, g_feat);
    cudaGetSymbolAddress((void**)&p_f,    g_f);
    cudaGetSymbolAddress((void**)&p_k,    g_k);
    cudaGetSymbolAddress((void**)&p_x123, g_x123);

    k_upsample_fuse<<<(BB*CC*HW + 255)/256, 256>>>(x_cur, x_lat);

    const int dils[3] = {1, 2, 4};
    for (int s = 0; s < 3; s++) {
        const float* cin = (s == 0) ? p_xsum : p_feat;
        k_fuse_weights<<<(9*CC*CQ + 255)/256, 256>>>(rw[s], rb[s], conv_w, conv_b);
        k_conv3x3<<<dim3(256, 4), 256>>>(cin, dils[s]);

        // graph reasoning on g_f -> x_{s+1}
        k_avgmax<<<2048, 256>>>();
        k_cw<<<BB, 128>>>(avg_w, max_w);
        k_gemm<<<dim3(256, 2), 256>>>(p_f, ck_w, ck_b, nullptr, p_k, CQ, MI, 1);
        k_zero_rs<<<(BB*HW + 255)/256, 256>>>();
        k_Arowsum<<<dim3(4, 4, BB), 256>>>();
        k_dinv<<<(BB*HW + 255)/256, 256>>>();
        k_transpose<<<dim3(8, 8, BB), dim3(32, 8)>>>();
        k_ptz<<<dim3(4, 2, BB), 256>>>();
        k_lx<<<dim3(4, 4, BB), 256>>>();
        k_y<<<dim3(4, 4, BB), 256>>>(gcn_w, s * CQ);

        if (s < 2)  // feature = conv1x1(f) + x_sum
            k_gemm<<<dim3(256, 16), 256>>>(p_f, conv1_w, conv1_b, p_xsum, p_feat, CQ, CC, 0);
    }

    // final: out = conv3_w @ concat(x1,x2,x3) + conv3_b
    k_gemm<<<dim3(256, 16), 256>>>(p_x123, conv3_w, conv3_b, nullptr, out, 3*CQ, CC, 0);
}

// round 2
// speedup vs baseline: 1.5747x; 1.5747x over previous
#include <cuda_runtime.h>
#include <math.h>

#define BB 64
#define CC 1024
#define CQ 256
#define MI 128
#define HW 256

// ---------------- scratch (device globals; no allocation allowed) ----------------
__device__ __align__(256) float g_xsum[BB*CC*HW];    // x_sum
__device__ __align__(256) float g_feat[BB*CC*HW];    // feature (stage 2/3 input)
__device__ __align__(256) float g_f   [BB*CQ*HW];    // current f_i  [b][c][hw]
__device__ __align__(256) float g_ft  [BB*HW*CQ];    // f transposed [b][i][c]
__device__ __align__(256) float g_wf  [9*CC*CQ];     // fused conv weights [t][c][o]
__device__ __align__(256) float g_bf  [CQ];
__device__ __align__(256) float g_k   [BB*MI*HW];    // relu(k) [b][m][i]
__device__ __align__(256) float g_cw  [BB*MI];
__device__ __align__(256) float g_scw [BB*MI];       // sqrt(cw)
__device__ __align__(256) float g_avg [BB*CQ];
__device__ __align__(256) float g_mx  [BB*CQ];
__device__ __align__(256) float g_rs  [BB*HW];       // row sums of sigmoid(A)
__device__ __align__(256) float g_dinv[BB*HW];       // rs^-0.5
__device__ __align__(256) float g_z   [BB*MI*CQ];    // cw ⊙ PtX
__device__ __align__(256) float g_lx  [BB*HW*CQ];    // LX [b][i][c]
__device__ __align__(256) float g_x123[BB*3*CQ*HW];  // concat(x1,x2,x3) [b][c][hw]

// ---------------- packed fp32x2 helpers (sm_100a FFMA2 path) ---------------------
typedef unsigned long long u64t;
__device__ __forceinline__ u64t pk2(float a, float b) {
    u64t r; asm("mov.b64 %0, {%1,%2};" : "=l"(r) : "f"(a), "f"(b)); return r;
}
__device__ __forceinline__ void upk2(u64t v, float& a, float& b) {
    asm("mov.b64 {%0,%1}, %2;" : "=f"(a), "=f"(b) : "l"(v));
}
__device__ __forceinline__ u64t fma2(u64t a, u64t b, u64t c) {
    u64t d; asm("fma.rn.f32x2 %0, %1, %2, %3;" : "=l"(d) : "l"(a), "l"(b), "l"(c)); return d;
}

// 16-deep K microloop: acc[u][p] (+)= Ws[k][ty*4+u] * Is[k][tx*4 + 2p..2p+1]
__device__ __forceinline__ void mm16(const float (*__restrict__ Ws)[64],
                                     const float (*__restrict__ Is)[64],
                                     int ty, int tx, u64t acc[4][2]) {
    #pragma unroll
    for (int kk = 0; kk < 16; kk++) {
        float4 a4 = *(const float4*)&Ws[kk][ty*4];
        float4 b4 = *(const float4*)&Is[kk][tx*4];
        u64t b01 = pk2(b4.x, b4.y);
        u64t b23 = pk2(b4.z, b4.w);
        u64t ad;
        ad = pk2(a4.x, a4.x); acc[0][0] = fma2(ad, b01, acc[0][0]); acc[0][1] = fma2(ad, b23, acc[0][1]);
        ad = pk2(a4.y, a4.y); acc[1][0] = fma2(ad, b01, acc[1][0]); acc[1][1] = fma2(ad, b23, acc[1][1]);
        ad = pk2(a4.z, a4.z); acc[2][0] = fma2(ad, b01, acc[2][0]); acc[2][1] = fma2(ad, b23, acc[2][1]);
        ad = pk2(a4.w, a4.w); acc[3][0] = fma2(ad, b01, acc[3][0]); acc[3][1] = fma2(ad, b23, acc[3][1]);
    }
}

// ---------------- upsample (align_corners) + fuse: x_sum = x_cur*(up+1) ----------
__global__ void k_upsample_fuse(const float* __restrict__ xc, const float* __restrict__ xl) {
    int idx = blockIdx.x * 256 + threadIdx.x;
    if (idx >= BB*CC*HW) return;
    int hw = idx & 255; int bc = idx >> 8;
    int y = hw >> 4, x = hw & 15;
    float ys = y * (7.0f / 15.0f);
    float xs = x * (7.0f / 15.0f);
    int y0 = (int)floorf(ys), x0 = (int)floorf(xs);
    int y1 = min(y0 + 1, 7), x1 = min(x0 + 1, 7);
    float wy = ys - (float)y0, wx = xs - (float)x0;
    const float* base = xl + (size_t)bc * 64;
    float v00 = base[y0*8+x0], v01 = base[y0*8+x1];
    float v10 = base[y1*8+x0], v11 = base[y1*8+x1];
    float top = v00*(1.f-wx) + v01*wx;
    float bot = v10*(1.f-wx) + v11*wx;
    float up  = top*(1.f-wy) + bot*wy;
    g_xsum[idx] = xc[idx] * (up + 1.0f);
}

// ------------- fold 1x1 into center tap of 3x3; layout wf[t][c][o] ---------------
__global__ void k_fuse_weights(const float* __restrict__ rw, const float* __restrict__ rb,
                               const float* __restrict__ cw, const float* __restrict__ cb) {
    int idx = blockIdx.x * 256 + threadIdx.x;   // over 9*1024*256
    if (idx >= 9*CC*CQ) return;
    int o = idx & 255; int tc = idx >> 8;
    int c = tc & 1023; int t = tc >> 10;
    float v = rw[((size_t)o*CC + c)*9 + t];
    if (t == 4) v += cw[(size_t)o*CC + c];
    g_wf[idx] = v;
    if (idx < CQ) g_bf[idx] = rb[idx] + cb[idx];
}

// ------------- dilated conv3x3 (fused 1x1): f = conv(in) + bf --------------------
// grid (256 n-tiles, 4 m-tiles), 256 threads, 64x64x16 tile, 4x4 micro
__global__ void __launch_bounds__(256) k_conv3x3(const float* __restrict__ in, int dil) {
    __shared__ __align__(16) float Ws[16][64];
    __shared__ __align__(16) float Is[16][64];
    int tid = threadIdx.x;
    int ty = tid >> 4, tx = tid & 15;
    int n0 = blockIdx.x * 64;
    int b = n0 >> 8, hw0 = n0 & 255;
    int m0 = blockIdx.y * 64;
    u64t acc[4][2] = {};
    const float* inb = in + (size_t)b * CC * HW;
    for (int t = 0; t < 9; t++) {
        int dy = dil * ((t / 3) - 1);
        int dx = dil * ((t % 3) - 1);
        for (int ck = 0; ck < CC; ck += 16) {
            #pragma unroll
            for (int r = 0; r < 4; r++) {
                int idx = tid + 256 * r;
                int kk = idx >> 6, col = idx & 63;
                Ws[kk][col] = g_wf[((size_t)t*CC + ck + kk)*CQ + m0 + col];
                int hw = hw0 + col;
                int y = (hw >> 4) + dy, x = (hw & 15) + dx;
                float v = 0.f;
                if ((unsigned)y < 16u && (unsigned)x < 16u)
                    v = inb[(size_t)(ck + kk)*HW + y*16 + x];
                Is[kk][col] = v;
            }
            __syncthreads();
            mm16(Ws, Is, ty, tx, acc);
            __syncthreads();
        }
    }
    #pragma unroll
    for (int u = 0; u < 4; u++) {
        int o = m0 + ty*4 + u;
        float bias = g_bf[o];
        float v0, v1, v2, v3;
        upk2(acc[u][0], v0, v1); upk2(acc[u][1], v2, v3);
        float* op = &g_f[((size_t)b*CQ + o)*HW + hw0 + tx*4];
        float4 o4 = make_float4(v0 + bias, v1 + bias, v2 + bias, v3 + bias);
        *(float4*)op = o4;
    }
}

// ------------- generic 1x1 GEMM over NCHW: out = [relu](W @ in + bias [+ add]) ---
__global__ void __launch_bounds__(256) k_gemm(const float* __restrict__ in, const float* __restrict__ Wt,
                       const float* __restrict__ bias, const float* __restrict__ add,
                       float* __restrict__ out, int Ci, int Co, int relu) {
    __shared__ __align__(16) float Ws[16][64];
    __shared__ __align__(16) float Is[16][64];
    int tid = threadIdx.x;
    int ty = tid >> 4, tx = tid & 15;
    int n0 = blockIdx.x * 64;
    int b = n0 >> 8, hw0 = n0 & 255;
    int m0 = blockIdx.y * 64;
    u64t acc[4][2] = {};
    const float* inb = in + (size_t)b * Ci * HW;
    for (int ck = 0; ck < Ci; ck += 16) {
        {   // weight tile via float4 (Ci multiple of 4, offsets 16-aligned)
            int mm = tid >> 2, k4 = (tid & 3) * 4;
            float4 w4 = *(const float4*)&Wt[(size_t)(m0 + mm)*Ci + ck + k4];
            Ws[k4+0][mm] = w4.x; Ws[k4+1][mm] = w4.y;
            Ws[k4+2][mm] = w4.z; Ws[k4+3][mm] = w4.w;
        }
        #pragma unroll
        for (int r = 0; r < 4; r++) {
            int idx = tid + 256 * r;
            int kk = idx >> 6, nn = idx & 63;
            Is[kk][nn] = inb[(size_t)(ck + kk)*HW + hw0 + nn];
        }
        __syncthreads();
        mm16(Ws, Is, ty, tx, acc);
        __syncthreads();
    }
    #pragma unroll
    for (int u = 0; u < 4; u++) {
        int o = m0 + ty*4 + u;
        float bi = bias[o];
        float v[4];
        upk2(acc[u][0], v[0], v[1]); upk2(acc[u][1], v[2], v[3]);
        size_t ob = ((size_t)b*Co + o)*HW + hw0 + tx*4;
        #pragma unroll
        for (int q = 0; q < 4; q++) {
            float vv = v[q] + bi;
            if (relu) vv = fmaxf(vv, 0.f);
            if (add) vv += add[ob + q];
            out[ob + q] = vv;
        }
    }
}

// ------------- per-(b,c) spatial mean/max over HW=256 (one warp each) ------------
__global__ void k_avgmax() {
    int gw = (blockIdx.x * blockDim.x + threadIdx.x) >> 5;
    int lane = threadIdx.x & 31;
    if (gw >= BB*CQ) return;
    const float* p = g_f + (size_t)gw * HW;
    float s = 0.f, m = -INFINITY;
    for (int i = lane; i < HW; i += 32) { float v = p[i]; s += v; m = fmaxf(m, v); }
    #pragma unroll
    for (int off = 16; off; off >>= 1) {
        s += __shfl_down_sync(0xffffffffu, s, off);
        m  = fmaxf(m, __shfl_down_sync(0xffffffffu, m, off));
    }
    if (lane == 0) { g_avg[gw] = s * (1.0f/256.0f); g_mx[gw] = m; }
}

// ------------- cw = sigmoid(relu(avg@avg_w^T) + relu(mx@max_w^T)) ----------------
__global__ void k_cw(const float* __restrict__ aw, const float* __restrict__ mw) {
    __shared__ float sa[CQ], sm[CQ];
    int b = blockIdx.x, m = threadIdx.x;
    for (int i = m; i < CQ; i += 128) {
        sa[i] = g_avg[b*CQ + i];
        sm[i] = g_mx [b*CQ + i];
    }
    __syncthreads();
    float s1 = 0.f, s2 = 0.f;
    for (int c = 0; c < CQ; c++) {
        s1 += sa[c] * aw[m*CQ + c];
        s2 += sm[c] * mw[m*CQ + c];
    }
    float val = fmaxf(s1, 0.f) + fmaxf(s2, 0.f);
    float cwv = 1.0f / (1.0f + expf(-val));
    g_cw [b*MI + m] = cwv;
    g_scw[b*MI + m] = sqrtf(cwv);
}

__global__ void k_zero_rs() {
    int idx = blockIdx.x * 256 + threadIdx.x;
    if (idx < BB*HW) g_rs[idx] = 0.f;
}

// ------------- row-sums of sigmoid(G^T G), G[m,i] = sqrt(cw[m])*k[m,i] -----------
// grid (4 j-tiles, 4 i-tiles, 64 batches)
__global__ void __launch_bounds__(256) k_Arowsum() {
    __shared__ __align__(16) float Gi[16][64];
    __shared__ __align__(16) float Gj[16][64];
    __shared__ float rsum[64];
    int tid = threadIdx.x;
    int ty = tid >> 4, tx = tid & 15;
    int b = blockIdx.z;
    int i0 = blockIdx.y * 64, j0 = blockIdx.x * 64;
    if (tid < 64) rsum[tid] = 0.f;
    u64t acc[4][2] = {};
    for (int mk = 0; mk < MI; mk += 16) {
        #pragma unroll
        for (int r = 0; r < 4; r++) {
            int idx = tid + 256 * r;
            int kk = idx >> 6, col = idx & 63;
            float sc = g_scw[b*MI + mk + kk];
            const float* krow = g_k + ((size_t)b*MI + mk + kk)*HW;
            Gi[kk][col] = krow[i0 + col] * sc;
            Gj[kk][col] = krow[j0 + col] * sc;
        }
        __syncthreads();
        mm16(Gi, Gj, ty, tx, acc);
        __syncthreads();
    }
    #pragma unroll
    for (int u = 0; u < 4; u++) {
        float v[4];
        upk2(acc[u][0], v[0], v[1]); upk2(acc[u][1], v[2], v[3]);
        float part = 0.f;
        #pragma unroll
        for (int q = 0; q < 4; q++)
            part += 1.0f / (1.0f + expf(-v[q]));
        atomicAdd(&rsum[ty*4 + u], part);
    }
    __syncthreads();
    if (tid < 64) atomicAdd(&g_rs[b*HW + i0 + tid], rsum[tid]);
}

__global__ void k_dinv() {
    int idx = blockIdx.x * 256 + threadIdx.x;
    if (idx < BB*HW) g_dinv[idx] = rsqrtf(g_rs[idx]);
}

// ------------- transpose f[b][c][i] -> ft[b][i][c] -------------------------------
__global__ void k_transpose() {
    __shared__ float t[32][33];
    int b = blockIdx.z;
    int c0 = blockIdx.x * 32, i0 = blockIdx.y * 32;
    for (int j = threadIdx.y; j < 32; j += 8)
        t[j][threadIdx.x] = g_f[((size_t)b*CQ + c0 + j)*HW + i0 + threadIdx.x];
    __syncthreads();
    for (int j = threadIdx.y; j < 32; j += 8)
        g_ft[((size_t)b*HW + i0 + j)*CQ + c0 + threadIdx.x] = t[threadIdx.x][j];
}

// ------------- Z[m,c] = cw[m] * sum_i d[i]*k[m,i]*ft[i,c] ------------------------
// grid (4 c-tiles, 2 m-tiles, 64)
__global__ void __launch_bounds__(256) k_ptz() {
    __shared__ __align__(16) float As[16][64];
    __shared__ __align__(16) float Bs[16][64];
    int tid = threadIdx.x;
    int ty = tid >> 4, tx = tid & 15;
    int b = blockIdx.z;
    int m0 = blockIdx.y * 64, c0 = blockIdx.x * 64;
    u64t acc[4][2] = {};
    for (int ik = 0; ik < HW; ik += 16) {
        {
            int mm = tid >> 2, k4 = (tid & 3) * 4;
            const float* krow = g_k + ((size_t)b*MI + m0 + mm)*HW + ik + k4;
            float4 k4v = *(const float4*)krow;
            const float* dv = g_dinv + b*HW + ik + k4;
            As[k4+0][mm] = k4v.x * dv[0];
            As[k4+1][mm] = k4v.y * dv[1];
            As[k4+2][mm] = k4v.z * dv[2];
            As[k4+3][mm] = k4v.w * dv[3];
        }
        #pragma unroll
        for (int r = 0; r < 4; r++) {
            int idx = tid + 256 * r;
            int kk = idx >> 6, nn = idx & 63;
            Bs[kk][nn] = g_ft[((size_t)b*HW + ik + kk)*CQ + c0 + nn];
        }
        __syncthreads();
        mm16(As, Bs, ty, tx, acc);
        __syncthreads();
    }
    #pragma unroll
    for (int u = 0; u < 4; u++) {
        int m = m0 + ty*4 + u;
        float cwm = g_cw[b*MI + m];
        float v[4];
        upk2(acc[u][0], v[0], v[1]); upk2(acc[u][1], v[2], v[3]);
        float* op = &g_z[((size_t)b*MI + m)*CQ + c0 + tx*4];
        *(float4*)op = make_float4(v[0]*cwm, v[1]*cwm, v[2]*cwm, v[3]*cwm);
    }
}

// ------------- LX[i,c] = ft[i,c] - d[i]*sum_m k[m,i]*Z[m,c] ----------------------
// grid (4 c-tiles, 4 i-tiles, 64)
__global__ void __launch_bounds__(256) k_lx() {
    __shared__ __align__(16) float As[16][64];
    __shared__ __align__(16) float Bs[16][64];
    int tid = threadIdx.x;
    int ty = tid >> 4, tx = tid & 15;
    int b = blockIdx.z;
    int i0 = blockIdx.y * 64, c0 = blockIdx.x * 64;
    u64t acc[4][2] = {};
    for (int mk = 0; mk < MI; mk += 16) {
        #pragma unroll
        for (int r = 0; r < 4; r++) {
            int idx = tid + 256 * r;
            int kk = idx >> 6, col = idx & 63;
            As[kk][col] = g_k[((size_t)b*MI + mk + kk)*HW + i0 + col];
            Bs[kk][col] = g_z[((size_t)b*MI + mk + kk)*CQ + c0 + col];
        }
        __syncthreads();
        mm16(As, Bs, ty, tx, acc);
        __syncthreads();
    }
    #pragma unroll
    for (int u = 0; u < 4; u++) {
        int i = i0 + ty*4 + u;
        float di = g_dinv[b*HW + i];
        float v[4];
        upk2(acc[u][0], v[0], v[1]); upk2(acc[u][1], v[2], v[3]);
        size_t oi = ((size_t)b*HW + i)*CQ + c0 + tx*4;
        float4 f4 = *(const float4*)&g_ft[oi];
        *(float4*)&g_lx[oi] = make_float4(f4.x - di*v[0], f4.y - di*v[1],
                                          f4.z - di*v[2], f4.w - di*v[3]);
    }
}

// ------------- Y = ft + LX @ gcn_w ; store transposed into x123 ------------------
// grid (4 c-tiles, 4 i-tiles, 64)
__global__ void __launch_bounds__(256) k_y(const float* __restrict__ gcn, int soff) {
    __shared__ __align__(16) float As[16][64];
    __shared__ __align__(16) float Bs[16][64];
    int tid = threadIdx.x;
    int ty = tid >> 4, tx = tid & 15;
    int b = blockIdx.z;
    int i0 = blockIdx.y * 64, c0 = blockIdx.x * 64;
    u64t acc[4][2] = {};
    for (int ck = 0; ck < CQ; ck += 16) {
        {
            int mm = tid >> 2, k4 = (tid & 3) * 4;
            float4 a4 = *(const float4*)&g_lx[((size_t)b*HW + i0 + mm)*CQ + ck + k4];
            As[k4+0][mm] = a4.x; As[k4+1][mm] = a4.y;
            As[k4+2][mm] = a4.z; As[k4+3][mm] = a4.w;
        }
        #pragma unroll
        for (int r = 0; r < 4; r++) {
            int idx = tid + 256 * r;
            int kk = idx >> 6, nn = idx & 63;
            Bs[kk][nn] = gcn[(size_t)(ck + kk)*CQ + c0 + nn];
        }
        __syncthreads();
        mm16(As, Bs, ty, tx, acc);
        __syncthreads();
    }
    #pragma unroll
    for (int u = 0; u < 4; u++) {
        int i = i0 + ty*4 + u;
        float v[4];
        upk2(acc[u][0], v[0], v[1]); upk2(acc[u][1], v[2], v[3]);
        #pragma unroll
        for (int q = 0; q < 4; q++) {
            int c = c0 + tx*4 + q;
            float val = g_ft[((size_t)b*HW + i)*CQ + c] + v[q];
            g_x123[((size_t)b*(3*CQ) + soff + c)*HW + i] = val;
        }
    }
}

// ---------------------------------------------------------------------------------
extern "C" void kernel_launch(void* const* d_in, const int* in_sizes, int n_in,
                              void* d_out, int out_size) {
    (void)in_sizes; (void)n_in; (void)out_size;
    const float* x_cur  = (const float*)d_in[0];
    const float* x_lat  = (const float*)d_in[1];
    const float* conv_w = (const float*)d_in[2];
    const float* conv_b = (const float*)d_in[3];
    const float* conv1_w= (const float*)d_in[4];
    const float* conv1_b= (const float*)d_in[5];
    const float* conv3_w= (const float*)d_in[6];
    const float* conv3_b= (const float*)d_in[7];
    const float* rw[3]  = {(const float*)d_in[8], (const float*)d_in[10], (const float*)d_in[12]};
    const float* rb[3]  = {(const float*)d_in[9], (const float*)d_in[11], (const float*)d_in[13]};
    const float* ck_w   = (const float*)d_in[14];
    const float* ck_b   = (const float*)d_in[15];
    const float* avg_w  = (const float*)d_in[16];
    const float* max_w  = (const float*)d_in[17];
    const float* gcn_w  = (const float*)d_in[18];
    float* out = (float*)d_out;

    float *p_xsum, *p_feat, *p_f, *p_k, *p_x123;
    cudaGetSymbolAddress((void**)&p_xsum, g_xsum);
    cudaGetSymbolAddress((void**)&p_feat, g_feat);
    cudaGetSymbolAddress((void**)&p_f,    g_f);
    cudaGetSymbolAddress((void**)&p_k,    g_k);
    cudaGetSymbolAddress((void**)&p_x123, g_x123);

    k_upsample_fuse<<<(BB*CC*HW + 255)/256, 256>>>(x_cur, x_lat);

    const int dils[3] = {1, 2, 4};
    for (int s = 0; s < 3; s++) {
        const float* cin = (s == 0) ? p_xsum : p_feat;
        k_fuse_weights<<<(9*CC*CQ + 255)/256, 256>>>(rw[s], rb[s], conv_w, conv_b);
        k_conv3x3<<<dim3(256, 4), 256>>>(cin, dils[s]);

        // graph reasoning on g_f -> x_{s+1}
        k_avgmax<<<2048, 256>>>();
        k_cw<<<BB, 128>>>(avg_w, max_w);
        k_gemm<<<dim3(256, 2), 256>>>(p_f, ck_w, ck_b, nullptr, p_k, CQ, MI, 1);
        k_zero_rs<<<(BB*HW + 255)/256, 256>>>();
        k_Arowsum<<<dim3(4, 4, BB), 256>>>();
        k_dinv<<<(BB*HW + 255)/256, 256>>>();
        k_transpose<<<dim3(8, 8, BB), dim3(32, 8)>>>();
        k_ptz<<<dim3(4, 2, BB), 256>>>();
        k_lx<<<dim3(4, 4, BB), 256>>>();
        k_y<<<dim3(4, 4, BB), 256>>>(gcn_w, s * CQ);

        if (s < 2)  // feature = conv1x1(f) + x_sum
            k_gemm<<<dim3(256, 16), 256>>>(p_f, conv1_w, conv1_b, p_xsum, p_feat, CQ, CC, 0);
    }

    // final: out = conv3_w @ concat(x1,x2,x3) + conv3_b
    k_gemm<<<dim3(256, 16), 256>>>(p_x123, conv3_w, conv3_b, nullptr, out, 3*CQ, CC, 0);
}

// round 6
// speedup vs baseline: 2.1819x; 1.3856x over previous
#include <cuda_runtime.h>
#include <cuda_bf16.h>
#include <math.h>
#include <stdint.h>

#define BB 64
#define CC 1024
#define CQ 256
#define MI 128
#define HW 256

// ---------------- scratch (device globals; no allocation allowed) ----------------
__device__ __align__(256) float g_xsum[BB*CC*HW];    // x_sum
__device__ __align__(256) float g_feat[BB*CC*HW];    // feature (stage 2/3 input)
__device__ __align__(256) float g_f   [BB*CQ*HW];    // current f_i  [b][c][hw]
__device__ __align__(256) float g_ft  [BB*HW*CQ];    // f transposed [b][i][c]
__device__ __align__(256) float g_wf  [9*CC*CQ];     // fused conv weights [t][c][o]
__device__ __align__(256) float g_bf  [CQ];
__device__ __align__(256) float g_k   [BB*MI*HW];    // relu(k) [b][m][i]
__device__ __align__(256) float g_cw  [BB*MI];
__device__ __align__(256) float g_scw [BB*MI];       // sqrt(cw)
__device__ __align__(256) float g_avg [BB*CQ];
__device__ __align__(256) float g_mx  [BB*CQ];
__device__ __align__(256) float g_rs  [BB*HW];       // row sums of sigmoid(A)
__device__ __align__(256) float g_dinv[BB*HW];       // rs^-0.5
__device__ __align__(256) float g_z   [BB*MI*CQ];    // cw ⊙ PtX
__device__ __align__(256) float g_lx  [BB*HW*CQ];    // LX [b][i][c]
__device__ __align__(256) float g_x123[BB*3*CQ*HW];  // concat(x1,x2,x3) [b][c][hw]

// ---------------- packed fp32x2 helpers (FFMA2 path) -----------------------------
typedef unsigned long long u64t;
__device__ __forceinline__ u64t pk2(float a, float b) {
    u64t r; asm("mov.b64 %0, {%1,%2};" : "=l"(r) : "f"(a), "f"(b)); return r;
}
__device__ __forceinline__ void upk2(u64t v, float& a, float& b) {
    asm("mov.b64 {%0,%1}, %2;" : "=f"(a), "=f"(b) : "l"(v));
}
__device__ __forceinline__ u64t fma2(u64t a, u64t b, u64t c) {
    u64t d; asm("fma.rn.f32x2 %0, %1, %2, %3;" : "=l"(d) : "l"(a), "l"(b), "l"(c)); return d;
}

__device__ __forceinline__ void mm16(const float (*__restrict__ Ws)[64],
                                     const float (*__restrict__ Is)[64],
                                     int ty, int tx, u64t acc[4][2]) {
    #pragma unroll
    for (int kk = 0; kk < 16; kk++) {
        float4 a4 = *(const float4*)&Ws[kk][ty*4];
        float4 b4 = *(const float4*)&Is[kk][tx*4];
        u64t b01 = pk2(b4.x, b4.y);
        u64t b23 = pk2(b4.z, b4.w);
        u64t ad;
        ad = pk2(a4.x, a4.x); acc[0][0] = fma2(ad, b01, acc[0][0]); acc[0][1] = fma2(ad, b23, acc[0][1]);
        ad = pk2(a4.y, a4.y); acc[1][0] = fma2(ad, b01, acc[1][0]); acc[1][1] = fma2(ad, b23, acc[1][1]);
        ad = pk2(a4.z, a4.z); acc[2][0] = fma2(ad, b01, acc[2][0]); acc[2][1] = fma2(ad, b23, acc[2][1]);
        ad = pk2(a4.w, a4.w); acc[3][0] = fma2(ad, b01, acc[3][0]); acc[3][1] = fma2(ad, b23, acc[3][1]);
    }
}

// ---------------- bf16 mma.sync helpers ------------------------------------------
__device__ __forceinline__ void mma16816(float d[4], const uint32_t a[4], const uint32_t b0, const uint32_t b1) {
    asm volatile("mma.sync.aligned.m16n8k16.row.col.f32.bf16.bf16.f32 "
        "{%0,%1,%2,%3}, {%4,%5,%6,%7}, {%8,%9}, {%0,%1,%2,%3};"
        : "+f"(d[0]), "+f"(d[1]), "+f"(d[2]), "+f"(d[3])
        : "r"(a[0]), "r"(a[1]), "r"(a[2]), "r"(a[3]), "r"(b0), "r"(b1));
}

// ------------- tensor-core dilated conv3x3 (fused 1x1), bf16x3 split -------------
// grid (128, 2): bx -> (b = bx>>1, hw0 = (bx&1)*128); by -> m0 = by*128
// CTA tile: M=128 oc x N=128 hw, K = 9 taps x 1024 ch (KC=32 chunks)
// 8 warps as 2(m) x 4(n): each warp 64x32, 4x4 m16n8k16 tiles
#define SPITCH 17   // u32 stride per row (16 k-pairs + 1 pad)
__global__ void __launch_bounds__(256) k_conv_mma(const float* __restrict__ in, int dil) {
    __shared__ uint32_t Ah[128*SPITCH], Al[128*SPITCH];
    __shared__ uint32_t Bh[128*SPITCH], Bl[128*SPITCH];
    int tid = threadIdx.x;
    int wid = tid >> 5, lane = tid & 31;
    int gid = lane >> 2, q = lane & 3;
    int warp_m = wid >> 2, warp_n = wid & 3;
    int bb  = blockIdx.x >> 1;
    int hw0 = (blockIdx.x & 1) * 128;
    int m0  = blockIdx.y * 128;
    const float* inb = in + (size_t)bb * CC * HW;

    float acc[4][4][4];
    #pragma unroll
    for (int mt = 0; mt < 4; mt++)
        #pragma unroll
        for (int nt = 0; nt < 4; nt++)
            #pragma unroll
            for (int e = 0; e < 4; e++) acc[mt][nt][e] = 0.f;

    __nv_bfloat16* Ah16 = (__nv_bfloat16*)Ah;
    __nv_bfloat16* Al16 = (__nv_bfloat16*)Al;
    __nv_bfloat16* Bh16 = (__nv_bfloat16*)Bh;
    __nv_bfloat16* Bl16 = (__nv_bfloat16*)Bl;

    for (int t = 0; t < 9; t++) {
        int dy = dil * ((t / 3) - 1);
        int dx = dil * ((t % 3) - 1);
        for (int ck = 0; ck < CC; ck += 32) {
            __syncthreads();   // previous mma phase done reading smem
            // ---- staging: 32 k x 128 rows for A (weights) and B (inputs) ----
            #pragma unroll
            for (int r = 0; r < 16; r++) {
                int idx = tid + 256 * r;        // 0..4095
                int o  = idx & 127;             // row (m or n)
                int cl = idx >> 7;              // k within chunk, 0..31
                int h16 = (o * SPITCH + (cl >> 1)) * 2 + (cl & 1);
                float w = g_wf[((size_t)t*CC + ck + cl)*CQ + m0 + o];
                __nv_bfloat16 wh = __float2bfloat16(w);
                Ah16[h16] = wh;
                Al16[h16] = __float2bfloat16(w - __bfloat162float(wh));
                int hw = hw0 + o;
                int y = (hw >> 4) + dy, x = (hw & 15) + dx;
                float v = 0.f;
                if ((unsigned)y < 16u && (unsigned)x < 16u)
                    v = inb[(size_t)(ck + cl)*HW + y*16 + x];
                __nv_bfloat16 vh = __float2bfloat16(v);
                Bh16[h16] = vh;
                Bl16[h16] = __float2bfloat16(v - __bfloat162float(vh));
            }
            __syncthreads();
            // ---- mma phase: two k16 steps ----
            #pragma unroll
            for (int s = 0; s < 2; s++) {
                int kb = s * 8 + q;
                uint32_t afh[4][4], afl[4][4];
                #pragma unroll
                for (int mt = 0; mt < 4; mt++) {
                    int mrow = warp_m*64 + mt*16 + gid;
                    int base = mrow * SPITCH + kb;
                    afh[mt][0] = Ah[base];              afh[mt][1] = Ah[base + 8*SPITCH];
                    afh[mt][2] = Ah[base + 4];          afh[mt][3] = Ah[base + 8*SPITCH + 4];
                    afl[mt][0] = Al[base];              afl[mt][1] = Al[base + 8*SPITCH];
                    afl[mt][2] = Al[base + 4];          afl[mt][3] = Al[base + 8*SPITCH + 4];
                }
                uint32_t bfh[4][2], bfl[4][2];
                #pragma unroll
                for (int nt = 0; nt < 4; nt++) {
                    int n = warp_n*32 + nt*8 + gid;
                    int base = n * SPITCH + kb;
                    bfh[nt][0] = Bh[base]; bfh[nt][1] = Bh[base + 4];
                    bfl[nt][0] = Bl[base]; bfl[nt][1] = Bl[base + 4];
                }
                #pragma unroll
                for (int mt = 0; mt < 4; mt++)
                    #pragma unroll
                    for (int nt = 0; nt < 4; nt++) {
                        mma16816(acc[mt][nt], afh[mt], bfh[nt][0], bfh[nt][1]);
                        mma16816(acc[mt][nt], afh[mt], bfl[nt][0], bfl[nt][1]);
                        mma16816(acc[mt][nt], afl[mt], bfh[nt][0], bfh[nt][1]);
                    }
            }
        }
    }
    // ---- epilogue: D[gid][2q,2q+1] & D[gid+8][...] per tile, + bias ----
    #pragma unroll
    for (int mt = 0; mt < 4; mt++) {
        int oc = m0 + warp_m*64 + mt*16 + gid;
        float bi0 = g_bf[oc], bi1 = g_bf[oc + 8];
        #pragma unroll
        for (int nt = 0; nt < 4; nt++) {
            int hw = hw0 + warp_n*32 + nt*8 + 2*q;
            float2 v0 = make_float2(acc[mt][nt][0] + bi0, acc[mt][nt][1] + bi0);
            *(float2*)&g_f[((size_t)bb*CQ + oc)*HW + hw] = v0;
            float2 v1 = make_float2(acc[mt][nt][2] + bi1, acc[mt][nt][3] + bi1);
            *(float2*)&g_f[((size_t)bb*CQ + oc + 8)*HW + hw] = v1;
        }
    }
}

// ---------------- upsample (align_corners) + fuse: x_sum = x_cur*(up+1) ----------
__global__ void k_upsample_fuse(const float* __restrict__ xc, const float* __restrict__ xl) {
    int idx = blockIdx.x * 256 + threadIdx.x;
    if (idx >= BB*CC*HW) return;
    int hw = idx & 255; int bc = idx >> 8;
    int y = hw >> 4, x = hw & 15;
    float ys = y * (7.0f / 15.0f);
    float xs = x * (7.0f / 15.0f);
    int y0 = (int)floorf(ys), x0 = (int)floorf(xs);
    int y1 = min(y0 + 1, 7), x1 = min(x0 + 1, 7);
    float wy = ys - (float)y0, wx = xs - (float)x0;
    const float* base = xl + (size_t)bc * 64;
    float v00 = base[y0*8+x0], v01 = base[y0*8+x1];
    float v10 = base[y1*8+x0], v11 = base[y1*8+x1];
    float top = v00*(1.f-wx) + v01*wx;
    float bot = v10*(1.f-wx) + v11*wx;
    float up  = top*(1.f-wy) + bot*wy;
    g_xsum[idx] = xc[idx] * (up + 1.0f);
}

// ------------- fold 1x1 into center tap of 3x3; layout wf[t][c][o] ---------------
__global__ void k_fuse_weights(const float* __restrict__ rw, const float* __restrict__ rb,
                               const float* __restrict__ cw, const float* __restrict__ cb) {
    int idx = blockIdx.x * 256 + threadIdx.x;   // over 9*1024*256
    if (idx >= 9*CC*CQ) return;
    int o = idx & 255; int tc = idx >> 8;
    int c = tc & 1023; int t = tc >> 10;
    float v = rw[((size_t)o*CC + c)*9 + t];
    if (t == 4) v += cw[(size_t)o*CC + c];
    g_wf[idx] = v;
    if (idx < CQ) g_bf[idx] = rb[idx] + cb[idx];
}

// ------------- generic 1x1 GEMM over NCHW: out = [relu](W @ in + bias [+ add]) ---
__global__ void __launch_bounds__(256) k_gemm(const float* __restrict__ in, const float* __restrict__ Wt,
                       const float* __restrict__ bias, const float* __restrict__ add,
                       float* __restrict__ out, int Ci, int Co, int relu) {
    __shared__ __align__(16) float Ws[16][64];
    __shared__ __align__(16) float Is[16][64];
    int tid = threadIdx.x;
    int ty = tid >> 4, tx = tid & 15;
    int n0 = blockIdx.x * 64;
    int b = n0 >> 8, hw0 = n0 & 255;
    int m0 = blockIdx.y * 64;
    u64t acc[4][2] = {};
    const float* inb = in + (size_t)b * Ci * HW;
    for (int ck = 0; ck < Ci; ck += 16) {
        {
            int mm = tid >> 2, k4 = (tid & 3) * 4;
            float4 w4 = *(const float4*)&Wt[(size_t)(m0 + mm)*Ci + ck + k4];
            Ws[k4+0][mm] = w4.x; Ws[k4+1][mm] = w4.y;
            Ws[k4+2][mm] = w4.z; Ws[k4+3][mm] = w4.w;
        }
        #pragma unroll
        for (int r = 0; r < 4; r++) {
            int idx = tid + 256 * r;
            int kk = idx >> 6, nn = idx & 63;
            Is[kk][nn] = inb[(size_t)(ck + kk)*HW + hw0 + nn];
        }
        __syncthreads();
        mm16(Ws, Is, ty, tx, acc);
        __syncthreads();
    }
    #pragma unroll
    for (int u = 0; u < 4; u++) {
        int o = m0 + ty*4 + u;
        float bi = bias[o];
        float v[4];
        upk2(acc[u][0], v[0], v[1]); upk2(acc[u][1], v[2], v[3]);
        size_t ob = ((size_t)b*Co + o)*HW + hw0 + tx*4;
        #pragma unroll
        for (int q = 0; q < 4; q++) {
            float vv = v[q] + bi;
            if (relu) vv = fmaxf(vv, 0.f);
            if (add) vv += add[ob + q];
            out[ob + q] = vv;
        }
    }
}

// ------------- per-(b,c) spatial mean/max over HW=256 (one warp each) ------------
__global__ void k_avgmax() {
    int gw = (blockIdx.x * blockDim.x + threadIdx.x) >> 5;
    int lane = threadIdx.x & 31;
    if (gw >= BB*CQ) return;
    const float* p = g_f + (size_t)gw * HW;
    float s = 0.f, m = -INFINITY;
    for (int i = lane; i < HW; i += 32) { float v = p[i]; s += v; m = fmaxf(m, v); }
    #pragma unroll
    for (int off = 16; off; off >>= 1) {
        s += __shfl_down_sync(0xffffffffu, s, off);
        m  = fmaxf(m, __shfl_down_sync(0xffffffffu, m, off));
    }
    if (lane == 0) { g_avg[gw] = s * (1.0f/256.0f); g_mx[gw] = m; }
}

// ------------- cw = sigmoid(relu(avg@avg_w^T) + relu(mx@max_w^T)) ----------------
__global__ void k_cw(const float* __restrict__ aw, const float* __restrict__ mw) {
    __shared__ float sa[CQ], sm[CQ];
    int b = blockIdx.x, m = threadIdx.x;
    for (int i = m; i < CQ; i += 128) {
        sa[i] = g_avg[b*CQ + i];
        sm[i] = g_mx [b*CQ + i];
    }
    __syncthreads();
    float s1 = 0.f, s2 = 0.f;
    for (int c = 0; c < CQ; c++) {
        s1 += sa[c] * aw[m*CQ + c];
        s2 += sm[c] * mw[m*CQ + c];
    }
    float val = fmaxf(s1, 0.f) + fmaxf(s2, 0.f);
    float cwv = 1.0f / (1.0f + expf(-val));
    g_cw [b*MI + m] = cwv;
    g_scw[b*MI + m] = sqrtf(cwv);
}

__global__ void k_zero_rs() {
    int idx = blockIdx.x * 256 + threadIdx.x;
    if (idx < BB*HW) g_rs[idx] = 0.f;
}

// ------------- row-sums of sigmoid(G^T G), G[m,i] = sqrt(cw[m])*k[m,i] -----------
__global__ void __launch_bounds__(256) k_Arowsum() {
    __shared__ __align__(16) float Gi[16][64];
    __shared__ __align__(16) float Gj[16][64];
    __shared__ float rsum[64];
    int tid = threadIdx.x;
    int ty = tid >> 4, tx = tid & 15;
    int b = blockIdx.z;
    int i0 = blockIdx.y * 64, j0 = blockIdx.x * 64;
    if (tid < 64) rsum[tid] = 0.f;
    u64t acc[4][2] = {};
    for (int mk = 0; mk < MI; mk += 16) {
        #pragma unroll
        for (int r = 0; r < 4; r++) {
            int idx = tid + 256 * r;
            int kk = idx >> 6, col = idx & 63;
            float sc = g_scw[b*MI + mk + kk];
            const float* krow = g_k + ((size_t)b*MI + mk + kk)*HW;
            Gi[kk][col] = krow[i0 + col] * sc;
            Gj[kk][col] = krow[j0 + col] * sc;
        }
        __syncthreads();
        mm16(Gi, Gj, ty, tx, acc);
        __syncthreads();
    }
    #pragma unroll
    for (int u = 0; u < 4; u++) {
        float v[4];
        upk2(acc[u][0], v[0], v[1]); upk2(acc[u][1], v[2], v[3]);
        float part = 0.f;
        #pragma unroll
        for (int q = 0; q < 4; q++)
            part += 1.0f / (1.0f + expf(-v[q]));
        atomicAdd(&rsum[ty*4 + u], part);
    }
    __syncthreads();
    if (tid < 64) atomicAdd(&g_rs[b*HW + i0 + tid], rsum[tid]);
}

__global__ void k_dinv() {
    int idx = blockIdx.x * 256 + threadIdx.x;
    if (idx < BB*HW) g_dinv[idx] = rsqrtf(g_rs[idx]);
}

// ------------- transpose f[b][c][i] -> ft[b][i][c] -------------------------------
__global__ void k_transpose() {
    __shared__ float t[32][33];
    int b = blockIdx.z;
    int c0 = blockIdx.x * 32, i0 = blockIdx.y * 32;
    for (int j = threadIdx.y; j < 32; j += 8)
        t[j][threadIdx.x] = g_f[((size_t)b*CQ + c0 + j)*HW + i0 + threadIdx.x];
    __syncthreads();
    for (int j = threadIdx.y; j < 32; j += 8)
        g_ft[((size_t)b*HW + i0 + j)*CQ + c0 + threadIdx.x] = t[threadIdx.x][j];
}

// ------------- Z[m,c] = cw[m] * sum_i d[i]*k[m,i]*ft[i,c] ------------------------
__global__ void __launch_bounds__(256) k_ptz() {
    __shared__ __align__(16) float As[16][64];
    __shared__ __align__(16) float Bs[16][64];
    int tid = threadIdx.x;
    int ty = tid >> 4, tx = tid & 15;
    int b = blockIdx.z;
    int m0 = blockIdx.y * 64, c0 = blockIdx.x * 64;
    u64t acc[4][2] = {};
    for (int ik = 0; ik < HW; ik += 16) {
        {
            int mm = tid >> 2, k4 = (tid & 3) * 4;
            const float* krow = g_k + ((size_t)b*MI + m0 + mm)*HW + ik + k4;
            float4 k4v = *(const float4*)krow;
            const float* dv = g_dinv + b*HW + ik + k4;
            As[k4+0][mm] = k4v.x * dv[0];
            As[k4+1][mm] = k4v.y * dv[1];
            As[k4+2][mm] = k4v.z * dv[2];
            As[k4+3][mm] = k4v.w * dv[3];
        }
        #pragma unroll
        for (int r = 0; r < 4; r++) {
            int idx = tid + 256 * r;
            int kk = idx >> 6, nn = idx & 63;
            Bs[kk][nn] = g_ft[((size_t)b*HW + ik + kk)*CQ + c0 + nn];
        }
        __syncthreads();
        mm16(As, Bs, ty, tx, acc);
        __syncthreads();
    }
    #pragma unroll
    for (int u = 0; u < 4; u++) {
        int m = m0 + ty*4 + u;
        float cwm = g_cw[b*MI + m];
        float v[4];
        upk2(acc[u][0], v[0], v[1]); upk2(acc[u][1], v[2], v[3]);
        float* op = &g_z[((size_t)b*MI + m)*CQ + c0 + tx*4];
        *(float4*)op = make_float4(v[0]*cwm, v[1]*cwm, v[2]*cwm, v[3]*cwm);
    }
}

// ------------- LX[i,c] = ft[i,c] - d[i]*sum_m k[m,i]*Z[m,c] ----------------------
__global__ void __launch_bounds__(256) k_lx() {
    __shared__ __align__(16) float As[16][64];
    __shared__ __align__(16) float Bs[16][64];
    int tid = threadIdx.x;
    int ty = tid >> 4, tx = tid & 15;
    int b = blockIdx.z;
    int i0 = blockIdx.y * 64, c0 = blockIdx.x * 64;
    u64t acc[4][2] = {};
    for (int mk = 0; mk < MI; mk += 16) {
        #pragma unroll
        for (int r = 0; r < 4; r++) {
            int idx = tid + 256 * r;
            int kk = idx >> 6, col = idx & 63;
            As[kk][col] = g_k[((size_t)b*MI + mk + kk)*HW + i0 + col];
            Bs[kk][col] = g_z[((size_t)b*MI + mk + kk)*CQ + c0 + col];
        }
        __syncthreads();
        mm16(As, Bs, ty, tx, acc);
        __syncthreads();
    }
    #pragma unroll
    for (int u = 0; u < 4; u++) {
        int i = i0 + ty*4 + u;
        float di = g_dinv[b*HW + i];
        float v[4];
        upk2(acc[u][0], v[0], v[1]); upk2(acc[u][1], v[2], v[3]);
        size_t oi = ((size_t)b*HW + i)*CQ + c0 + tx*4;
        float4 f4 = *(const float4*)&g_ft[oi];
        *(float4*)&g_lx[oi] = make_float4(f4.x - di*v[0], f4.y - di*v[1],
                                          f4.z - di*v[2], f4.w - di*v[3]);
    }
}

// ------------- Y = ft + LX @ gcn_w ; store transposed into x123 ------------------
__global__ void __launch_bounds__(256) k_y(const float* __restrict__ gcn, int soff) {
    __shared__ __align__(16) float As[16][64];
    __shared__ __align__(16) float Bs[16][64];
    int tid = threadIdx.x;
    int ty = tid >> 4, tx = tid & 15;
    int b = blockIdx.z;
    int i0 = blockIdx.y * 64, c0 = blockIdx.x * 64;
    u64t acc[4][2] = {};
    for (int ck = 0; ck < CQ; ck += 16) {
        {
            int mm = tid >> 2, k4 = (tid & 3) * 4;
            float4 a4 = *(const float4*)&g_lx[((size_t)b*HW + i0 + mm)*CQ + ck + k4];
            As[k4+0][mm] = a4.x; As[k4+1][mm] = a4.y;
            As[k4+2][mm] = a4.z; As[k4+3][mm] = a4.w;
        }
        #pragma unroll
        for (int r = 0; r < 4; r++) {
            int idx = tid + 256 * r;
            int kk = idx >> 6, nn = idx & 63;
            Bs[kk][nn] = gcn[(size_t)(ck + kk)*CQ + c0 + nn];
        }
        __syncthreads();
        mm16(As, Bs, ty, tx, acc);
        __syncthreads();
    }
    #pragma unroll
    for (int u = 0; u < 4; u++) {
        int i = i0 + ty*4 + u;
        float v[4];
        upk2(acc[u][0], v[0], v[1]); upk2(acc[u][1], v[2], v[3]);
        #pragma unroll
        for (int q = 0; q < 4; q++) {
            int c = c0 + tx*4 + q;
            float val = g_ft[((size_t)b*HW + i)*CQ + c] + v[q];
            g_x123[((size_t)b*(3*CQ) + soff + c)*HW + i] = val;
        }
    }
}

// ---------------------------------------------------------------------------------
extern "C" void kernel_launch(void* const* d_in, const int* in_sizes, int n_in,
                              void* d_out, int out_size) {
    (void)in_sizes; (void)n_in; (void)out_size;
    const float* x_cur  = (const float*)d_in[0];
    const float* x_lat  = (const float*)d_in[1];
    const float* conv_w = (const float*)d_in[2];
    const float* conv_b = (const float*)d_in[3];
    const float* conv1_w= (const float*)d_in[4];
    const float* conv1_b= (const float*)d_in[5];
    const float* conv3_w= (const float*)d_in[6];
    const float* conv3_b= (const float*)d_in[7];
    const float* rw[3]  = {(const float*)d_in[8], (const float*)d_in[10], (const float*)d_in[12]};
    const float* rb[3]  = {(const float*)d_in[9], (const float*)d_in[11], (const float*)d_in[13]};
    const float* ck_w   = (const float*)d_in[14];
    const float* ck_b   = (const float*)d_in[15];
    const float* avg_w  = (const float*)d_in[16];
    const float* max_w  = (const float*)d_in[17];
    const float* gcn_w  = (const float*)d_in[18];
    float* out = (float*)d_out;

    float *p_xsum, *p_feat, *p_f, *p_k, *p_x123;
    cudaGetSymbolAddress((void**)&p_xsum, g_xsum);
    cudaGetSymbolAddress((void**)&p_feat, g_feat);
    cudaGetSymbolAddress((void**)&p_f,    g_f);
    cudaGetSymbolAddress((void**)&p_k,    g_k);
    cudaGetSymbolAddress((void**)&p_x123, g_x123);

    k_upsample_fuse<<<(BB*CC*HW + 255)/256, 256>>>(x_cur, x_lat);

    const int dils[3] = {1, 2, 4};
    for (int s = 0; s < 3; s++) {
        const float* cin = (s == 0) ? p_xsum : p_feat;
        k_fuse_weights<<<(9*CC*CQ + 255)/256, 256>>>(rw[s], rb[s], conv_w, conv_b);
        k_conv_mma<<<dim3(128, 2), 256>>>(cin, dils[s]);

        // graph reasoning on g_f -> x_{s+1}
        k_avgmax<<<2048, 256>>>();
        k_cw<<<BB, 128>>>(avg_w, max_w);
        k_gemm<<<dim3(256, 2), 256>>>(p_f, ck_w, ck_b, nullptr, p_k, CQ, MI, 1);
        k_zero_rs<<<(BB*HW + 255)/256, 256>>>();
        k_Arowsum<<<dim3(4, 4, BB), 256>>>();
        k_dinv<<<(BB*HW + 255)/256, 256>>>();
        k_transpose<<<dim3(8, 8, BB), dim3(32, 8)>>>();
        k_ptz<<<dim3(4, 2, BB), 256>>>();
        k_lx<<<dim3(4, 4, BB), 256>>>();
        k_y<<<dim3(4, 4, BB), 256>>>(gcn_w, s * CQ);

        if (s < 2)  // feature = conv1x1(f) + x_sum
            k_gemm<<<dim3(256, 16), 256>>>(p_f, conv1_w, conv1_b, p_xsum, p_feat, CQ, CC, 0);
    }

    // final: out = conv3_w @ concat(x1,x2,x3) + conv3_b
    k_gemm<<<dim3(256, 16), 256>>>(p_x123, conv3_w, conv3_b, nullptr, out, 3*CQ, CC, 0);
}

// round 7
// speedup vs baseline: 2.7685x; 1.2689x over previous
#include <cuda_runtime.h>
#include <cuda_bf16.h>
#include <math.h>
#include <stdint.h>

#define BB 64
#define CC 1024
#define CQ 256
#define MI 128
#define HW 256

// ---------------- scratch (device globals; no allocation allowed) ----------------
__device__ __align__(256) float g_xsum[BB*CC*HW];    // x_sum
__device__ __align__(256) float g_feat[BB*CC*HW];    // feature (stage 2/3 input)
__device__ __align__(256) float g_f   [BB*CQ*HW];    // current f_i  [b][c][hw]
__device__ __align__(256) float g_ft  [BB*HW*CQ];    // f transposed [b][i][c]
__device__ __align__(256) float g_bf  [CQ];
__device__ __align__(256) float g_k   [BB*MI*HW];    // relu(k) [b][m][i]
__device__ __align__(256) float g_cw  [BB*MI];
__device__ __align__(256) float g_scw [BB*MI];       // sqrt(cw)
__device__ __align__(256) float g_avg [BB*CQ];
__device__ __align__(256) float g_mx  [BB*CQ];
__device__ __align__(256) float g_rs  [BB*HW];       // row sums of sigmoid(A)
__device__ __align__(256) float g_dinv[BB*HW];       // rs^-0.5
__device__ __align__(256) float g_z   [BB*MI*CQ];    // cw ⊙ PtX
__device__ __align__(256) float g_lx  [BB*HW*CQ];    // LX [b][i][c]
__device__ __align__(256) float g_x123[BB*3*CQ*HW];  // concat(x1,x2,x3) [b][c][hw]
// bf16 hi/lo splits for the tensor-core conv
__device__ __align__(256) __nv_bfloat16 g_wh [9*CQ*CC];   // weights [t][o][c]
__device__ __align__(256) __nv_bfloat16 g_wl [9*CQ*CC];
__device__ __align__(256) __nv_bfloat16 g_inh[BB*HW*CC];  // input  [b][hw][c]
__device__ __align__(256) __nv_bfloat16 g_inl[BB*HW*CC];

// ---------------- packed fp32x2 helpers (FFMA2 path) -----------------------------
typedef unsigned long long u64t;
__device__ __forceinline__ u64t pk2(float a, float b) {
    u64t r; asm("mov.b64 %0, {%1,%2};" : "=l"(r) : "f"(a), "f"(b)); return r;
}
__device__ __forceinline__ void upk2(u64t v, float& a, float& b) {
    asm("mov.b64 {%0,%1}, %2;" : "=f"(a), "=f"(b) : "l"(v));
}
__device__ __forceinline__ u64t fma2(u64t a, u64t b, u64t c) {
    u64t d; asm("fma.rn.f32x2 %0, %1, %2, %3;" : "=l"(d) : "l"(a), "l"(b), "l"(c)); return d;
}

__device__ __forceinline__ void mm16(const float (*__restrict__ Ws)[64],
                                     const float (*__restrict__ Is)[64],
                                     int ty, int tx, u64t acc[4][2]) {
    #pragma unroll
    for (int kk = 0; kk < 16; kk++) {
        float4 a4 = *(const float4*)&Ws[kk][ty*4];
        float4 b4 = *(const float4*)&Is[kk][tx*4];
        u64t b01 = pk2(b4.x, b4.y);
        u64t b23 = pk2(b4.z, b4.w);
        u64t ad;
        ad = pk2(a4.x, a4.x); acc[0][0] = fma2(ad, b01, acc[0][0]); acc[0][1] = fma2(ad, b23, acc[0][1]);
        ad = pk2(a4.y, a4.y); acc[1][0] = fma2(ad, b01, acc[1][0]); acc[1][1] = fma2(ad, b23, acc[1][1]);
        ad = pk2(a4.z, a4.z); acc[2][0] = fma2(ad, b01, acc[2][0]); acc[2][1] = fma2(ad, b23, acc[2][1]);
        ad = pk2(a4.w, a4.w); acc[3][0] = fma2(ad, b01, acc[3][0]); acc[3][1] = fma2(ad, b23, acc[3][1]);
    }
}

// ---------------- bf16 mma.sync + cp.async helpers -------------------------------
__device__ __forceinline__ void mma16816(float d[4], const uint32_t a[4], const uint32_t b0, const uint32_t b1) {
    asm volatile("mma.sync.aligned.m16n8k16.row.col.f32.bf16.bf16.f32 "
        "{%0,%1,%2,%3}, {%4,%5,%6,%7}, {%8,%9}, {%0,%1,%2,%3};"
        : "+f"(d[0]), "+f"(d[1]), "+f"(d[2]), "+f"(d[3])
        : "r"(a[0]), "r"(a[1]), "r"(a[2]), "r"(a[3]), "r"(b0), "r"(b1));
}
__device__ __forceinline__ uint32_t smem_u32(const void* p) {
    uint32_t a;
    asm("{ .reg .u64 t; cvta.to.shared.u64 t, %1; cvt.u32.u64 %0, t; }" : "=r"(a) : "l"(p));
    return a;
}
__device__ __forceinline__ void cp16(uint32_t dst, const void* src, int sz) {
    asm volatile("cp.async.cg.shared.global [%0], [%1], 16, %2;"
                 :: "r"(dst), "l"(src), "r"(sz) : "memory");
}
__device__ __forceinline__ void cp_commit() {
    asm volatile("cp.async.commit_group;" ::: "memory");
}
__device__ __forceinline__ void cp_wait1() {
    asm volatile("cp.async.wait_group 1;" ::: "memory");
}
__device__ __forceinline__ void cp_wait0() {
    asm volatile("cp.async.wait_group 0;" ::: "memory");
}

// ------------- tensor-core dilated conv3x3 (fused 1x1), bf16x3 split -------------
// grid (128, 2): bx -> (b = bx>>1, hw0 = (bx&1)*128); by -> m0 = by*128
// smem: double-buffered AH/AL/BH/BL tiles, 128 rows x 32 k bf16, row pitch 80B
#define CPITCH 80           // bytes per smem row (64B data + 16B pad -> conflict-free)
#define ABYTES (128*CPITCH) // 10240 per array
#define STAGEB (4*ABYTES)   // 40960 per pipeline stage
#define SMEM_CONV (2*STAGEB)

__device__ __forceinline__ void conv_stage(int tid, int m0, int hw0, int bb, int ch, int dil,
                                           uint32_t sAH, uint32_t sAL, uint32_t sBH, uint32_t sBL) {
    int t  = ch >> 5;
    int ck = (ch & 31) << 5;
    int dy = dil * ((t / 3) - 1);
    int dx = dil * ((t % 3) - 1);
    const char* wh = (const char*)g_wh;
    const char* wl = (const char*)g_wl;
    const char* ih = (const char*)g_inh;
    const char* il = (const char*)g_inl;
    #pragma unroll
    for (int i = 0; i < 2; i++) {
        int cid = tid + 256*i;          // 0..511
        int row = cid >> 2;             // 0..127
        int seg = (cid & 3) * 16;       // byte offset within 64B row
        size_t woff = (((size_t)(t*CQ + m0 + row))*CC + ck)*2 + seg;
        cp16(sAH + row*CPITCH + seg, wh + woff, 16);
        cp16(sAL + row*CPITCH + seg, wl + woff, 16);
        int hw = hw0 + row;
        int y = (hw >> 4) + dy, x = (hw & 15) + dx;
        int ok = ((unsigned)y < 16u) && ((unsigned)x < 16u);
        int ridx = ok ? (y*16 + x) : 0;
        int sz = ok ? 16 : 0;
        size_t ioff = (((size_t)(bb*HW + ridx))*CC + ck)*2 + seg;
        cp16(sBH + row*CPITCH + seg, ih + ioff, sz);
        cp16(sBL + row*CPITCH + seg, il + ioff, sz);
    }
}

__global__ void __launch_bounds__(256) k_conv_mma(int dil) {
    extern __shared__ char smem[];
    uint32_t sb = smem_u32(smem);
    int tid = threadIdx.x;
    int wid = tid >> 5, lane = tid & 31;
    int gid = lane >> 2, q = lane & 3;
    int warp_m = wid >> 2, warp_n = wid & 3;
    int bb  = blockIdx.x >> 1;
    int hw0 = (blockIdx.x & 1) * 128;
    int m0  = blockIdx.y * 128;

    float acc[4][4][4];
    #pragma unroll
    for (int mt = 0; mt < 4; mt++)
        #pragma unroll
        for (int nt = 0; nt < 4; nt++)
            #pragma unroll
            for (int e = 0; e < 4; e++) acc[mt][nt][e] = 0.f;

    const int NCH = 9 * 32;   // 288 chunks of K=32
    conv_stage(tid, m0, hw0, bb, 0, dil, sb, sb + ABYTES, sb + 2*ABYTES, sb + 3*ABYTES);
    cp_commit();

    for (int ch = 0; ch < NCH; ch++) {
        __syncthreads();            // all warps done reading buf (ch+1)&1 from mma(ch-1)
        if (ch + 1 < NCH) {
            uint32_t bs = sb + ((ch + 1) & 1) * STAGEB;
            conv_stage(tid, m0, hw0, bb, ch + 1, dil, bs, bs + ABYTES, bs + 2*ABYTES, bs + 3*ABYTES);
            cp_commit();
            cp_wait1();             // group ch complete (group ch+1 may be in flight)
        } else {
            cp_wait0();
        }
        __syncthreads();            // copies visible to all warps

        char* bufc = smem + (ch & 1) * STAGEB;
        const uint32_t* Ah = (const uint32_t*)(bufc);
        const uint32_t* Al = (const uint32_t*)(bufc + ABYTES);
        const uint32_t* Bh = (const uint32_t*)(bufc + 2*ABYTES);
        const uint32_t* Bl = (const uint32_t*)(bufc + 3*ABYTES);

        #pragma unroll
        for (int s = 0; s < 2; s++) {
            int kb = s * 8 + q;
            uint32_t afh[4][4], afl[4][4];
            #pragma unroll
            for (int mt = 0; mt < 4; mt++) {
                int base = (warp_m*64 + mt*16 + gid) * 20 + kb;
                afh[mt][0] = Ah[base];        afh[mt][1] = Ah[base + 160];
                afh[mt][2] = Ah[base + 4];    afh[mt][3] = Ah[base + 164];
                afl[mt][0] = Al[base];        afl[mt][1] = Al[base + 160];
                afl[mt][2] = Al[base + 4];    afl[mt][3] = Al[base + 164];
            }
            uint32_t bfh[4][2], bfl[4][2];
            #pragma unroll
            for (int nt = 0; nt < 4; nt++) {
                int base = (warp_n*32 + nt*8 + gid) * 20 + kb;
                bfh[nt][0] = Bh[base]; bfh[nt][1] = Bh[base + 4];
                bfl[nt][0] = Bl[base]; bfl[nt][1] = Bl[base + 4];
            }
            #pragma unroll
            for (int mt = 0; mt < 4; mt++)
                #pragma unroll
                for (int nt = 0; nt < 4; nt++) {
                    mma16816(acc[mt][nt], afh[mt], bfh[nt][0], bfh[nt][1]);
                    mma16816(acc[mt][nt], afh[mt], bfl[nt][0], bfl[nt][1]);
                    mma16816(acc[mt][nt], afl[mt], bfh[nt][0], bfh[nt][1]);
                }
        }
    }

    // ---- epilogue: D[gid][2q,2q+1] & D[gid+8][...] per tile, + bias ----
    #pragma unroll
    for (int mt = 0; mt < 4; mt++) {
        int oc = m0 + warp_m*64 + mt*16 + gid;
        float bi0 = g_bf[oc], bi1 = g_bf[oc + 8];
        #pragma unroll
        for (int nt = 0; nt < 4; nt++) {
            int hw = hw0 + warp_n*32 + nt*8 + 2*q;
            float2 v0 = make_float2(acc[mt][nt][0] + bi0, acc[mt][nt][1] + bi0);
            *(float2*)&g_f[((size_t)bb*CQ + oc)*HW + hw] = v0;
            float2 v1 = make_float2(acc[mt][nt][2] + bi1, acc[mt][nt][3] + bi1);
            *(float2*)&g_f[((size_t)bb*CQ + oc + 8)*HW + hw] = v1;
        }
    }
}

// ------------- fused weights -> bf16 hi/lo, transposed [t][o][c]; bias -----------
__global__ void k_fuse_weights2(const float* __restrict__ rw, const float* __restrict__ rb,
                                const float* __restrict__ cw, const float* __restrict__ cb) {
    int idx = blockIdx.x * 256 + threadIdx.x;   // over 9*256*1024, layout ((t*CQ+o)*CC+c)
    if (idx >= 9*CQ*CC) return;
    int c = idx & 1023;
    int to = idx >> 10;
    int o = to & 255;
    int t = to >> 8;
    float v = rw[((size_t)o*CC + c)*9 + t];
    if (t == 4) v += cw[(size_t)o*CC + c];
    __nv_bfloat16 vh = __float2bfloat16(v);
    g_wh[idx] = vh;
    g_wl[idx] = __float2bfloat16(v - __bfloat162float(vh));
    if (idx < CQ) g_bf[idx] = rb[idx] + cb[idx];
}

// ------------- split conv input into bf16 hi/lo, transposed [b][hw][c] -----------
__global__ void k_split_in(const float* __restrict__ in) {
    __shared__ float t32[32][33];
    int b = blockIdx.z;
    int c0 = blockIdx.x * 32, hw0 = blockIdx.y * 32;
    for (int j = threadIdx.y; j < 32; j += 8)
        t32[j][threadIdx.x] = in[((size_t)b*CC + c0 + j)*HW + hw0 + threadIdx.x];
    __syncthreads();
    for (int j = threadIdx.y; j < 32; j += 8) {
        float v = t32[threadIdx.x][j];
        __nv_bfloat16 vh = __float2bfloat16(v);
        size_t oi = ((size_t)b*HW + hw0 + j)*CC + c0 + threadIdx.x;
        g_inh[oi] = vh;
        g_inl[oi] = __float2bfloat16(v - __bfloat162float(vh));
    }
}

// ------------- generic 1x1 GEMM over NCHW: out = [relu](W @ in + bias [+ add]) ---
__global__ void __launch_bounds__(256) k_gemm(const float* __restrict__ in, const float* __restrict__ Wt,
                       const float* __restrict__ bias, const float* __restrict__ add,
                       float* __restrict__ out, int Ci, int Co, int relu) {
    __shared__ __align__(16) float Ws[16][64];
    __shared__ __align__(16) float Is[16][64];
    int tid = threadIdx.x;
    int ty = tid >> 4, tx = tid & 15;
    int n0 = blockIdx.x * 64;
    int b = n0 >> 8, hw0 = n0 & 255;
    int m0 = blockIdx.y * 64;
    u64t acc[4][2] = {};
    const float* inb = in + (size_t)b * Ci * HW;
    for (int ck = 0; ck < Ci; ck += 16) {
        {
            int mm = tid >> 2, k4 = (tid & 3) * 4;
            float4 w4 = *(const float4*)&Wt[(size_t)(m0 + mm)*Ci + ck + k4];
            Ws[k4+0][mm] = w4.x; Ws[k4+1][mm] = w4.y;
            Ws[k4+2][mm] = w4.z; Ws[k4+3][mm] = w4.w;
        }
        #pragma unroll
        for (int r = 0; r < 4; r++) {
            int idx = tid + 256 * r;
            int kk = idx >> 6, nn = idx & 63;
            Is[kk][nn] = inb[(size_t)(ck + kk)*HW + hw0 + nn];
        }
        __syncthreads();
        mm16(Ws, Is, ty, tx, acc);
        __syncthreads();
    }
    #pragma unroll
    for (int u = 0; u < 4; u++) {
        int o = m0 + ty*4 + u;
        float bi = bias[o];
        float v[4];
        upk2(acc[u][0], v[0], v[1]); upk2(acc[u][1], v[2], v[3]);
        size_t ob = ((size_t)b*Co + o)*HW + hw0 + tx*4;
        #pragma unroll
        for (int q = 0; q < 4; q++) {
            float vv = v[q] + bi;
            if (relu) vv = fmaxf(vv, 0.f);
            if (add) vv += add[ob + q];
            out[ob + q] = vv;
        }
    }
}

// ---------------- upsample (align_corners) + fuse: x_sum = x_cur*(up+1) ----------
__global__ void k_upsample_fuse(const float* __restrict__ xc, const float* __restrict__ xl) {
    int idx = blockIdx.x * 256 + threadIdx.x;
    if (idx >= BB*CC*HW) return;
    int hw = idx & 255; int bc = idx >> 8;
    int y = hw >> 4, x = hw & 15;
    float ys = y * (7.0f / 15.0f);
    float xs = x * (7.0f / 15.0f);
    int y0 = (int)floorf(ys), x0 = (int)floorf(xs);
    int y1 = min(y0 + 1, 7), x1 = min(x0 + 1, 7);
    float wy = ys - (float)y0, wx = xs - (float)x0;
    const float* base = xl + (size_t)bc * 64;
    float v00 = base[y0*8+x0], v01 = base[y0*8+x1];
    float v10 = base[y1*8+x0], v11 = base[y1*8+x1];
    float top = v00*(1.f-wx) + v01*wx;
    float bot = v10*(1.f-wx) + v11*wx;
    float up  = top*(1.f-wy) + bot*wy;
    g_xsum[idx] = xc[idx] * (up + 1.0f);
}

// ------------- per-(b,c) spatial mean/max over HW=256 (one warp each) ------------
__global__ void k_avgmax() {
    int gw = (blockIdx.x * blockDim.x + threadIdx.x) >> 5;
    int lane = threadIdx.x & 31;
    if (gw >= BB*CQ) return;
    const float* p = g_f + (size_t)gw * HW;
    float s = 0.f, m = -INFINITY;
    for (int i = lane; i < HW; i += 32) { float v = p[i]; s += v; m = fmaxf(m, v); }
    #pragma unroll
    for (int off = 16; off; off >>= 1) {
        s += __shfl_down_sync(0xffffffffu, s, off);
        m  = fmaxf(m, __shfl_down_sync(0xffffffffu, m, off));
    }
    if (lane == 0) { g_avg[gw] = s * (1.0f/256.0f); g_mx[gw] = m; }
}

// ------------- cw = sigmoid(relu(avg@avg_w^T) + relu(mx@max_w^T)) ----------------
__global__ void k_cw(const float* __restrict__ aw, const float* __restrict__ mw) {
    __shared__ float sa[CQ], sm[CQ];
    int b = blockIdx.x, m = threadIdx.x;
    for (int i = m; i < CQ; i += 128) {
        sa[i] = g_avg[b*CQ + i];
        sm[i] = g_mx [b*CQ + i];
    }
    __syncthreads();
    float s1 = 0.f, s2 = 0.f;
    for (int c = 0; c < CQ; c++) {
        s1 += sa[c] * aw[m*CQ + c];
        s2 += sm[c] * mw[m*CQ + c];
    }
    float val = fmaxf(s1, 0.f) + fmaxf(s2, 0.f);
    float cwv = 1.0f / (1.0f + expf(-val));
    g_cw [b*MI + m] = cwv;
    g_scw[b*MI + m] = sqrtf(cwv);
}

__global__ void k_zero_rs() {
    int idx = blockIdx.x * 256 + threadIdx.x;
    if (idx < BB*HW) g_rs[idx] = 0.f;
}

// ------------- row-sums of sigmoid(G^T G), G[m,i] = sqrt(cw[m])*k[m,i] -----------
__global__ void __launch_bounds__(256) k_Arowsum() {
    __shared__ __align__(16) float Gi[16][64];
    __shared__ __align__(16) float Gj[16][64];
    __shared__ float rsum[64];
    int tid = threadIdx.x;
    int ty = tid >> 4, tx = tid & 15;
    int b = blockIdx.z;
    int i0 = blockIdx.y * 64, j0 = blockIdx.x * 64;
    if (tid < 64) rsum[tid] = 0.f;
    u64t acc[4][2] = {};
    for (int mk = 0; mk < MI; mk += 16) {
        #pragma unroll
        for (int r = 0; r < 4; r++) {
            int idx = tid + 256 * r;
            int kk = idx >> 6, col = idx & 63;
            float sc = g_scw[b*MI + mk + kk];
            const float* krow = g_k + ((size_t)b*MI + mk + kk)*HW;
            Gi[kk][col] = krow[i0 + col] * sc;
            Gj[kk][col] = krow[j0 + col] * sc;
        }
        __syncthreads();
        mm16(Gi, Gj, ty, tx, acc);
        __syncthreads();
    }
    #pragma unroll
    for (int u = 0; u < 4; u++) {
        float v[4];
        upk2(acc[u][0], v[0], v[1]); upk2(acc[u][1], v[2], v[3]);
        float part = 0.f;
        #pragma unroll
        for (int q = 0; q < 4; q++)
            part += 1.0f / (1.0f + expf(-v[q]));
        atomicAdd(&rsum[ty*4 + u], part);
    }
    __syncthreads();
    if (tid < 64) atomicAdd(&g_rs[b*HW + i0 + tid], rsum[tid]);
}

__global__ void k_dinv() {
    int idx = blockIdx.x * 256 + threadIdx.x;
    if (idx < BB*HW) g_dinv[idx] = rsqrtf(g_rs[idx]);
}

// ------------- transpose f[b][c][i] -> ft[b][i][c] -------------------------------
__global__ void k_transpose() {
    __shared__ float t[32][33];
    int b = blockIdx.z;
    int c0 = blockIdx.x * 32, i0 = blockIdx.y * 32;
    for (int j = threadIdx.y; j < 32; j += 8)
        t[j][threadIdx.x] = g_f[((size_t)b*CQ + c0 + j)*HW + i0 + threadIdx.x];
    __syncthreads();
    for (int j = threadIdx.y; j < 32; j += 8)
        g_ft[((size_t)b*HW + i0 + j)*CQ + c0 + threadIdx.x] = t[threadIdx.x][j];
}

// ------------- Z[m,c] = cw[m] * sum_i d[i]*k[m,i]*ft[i,c] ------------------------
__global__ void __launch_bounds__(256) k_ptz() {
    __shared__ __align__(16) float As[16][64];
    __shared__ __align__(16) float Bs[16][64];
    int tid = threadIdx.x;
    int ty = tid >> 4, tx = tid & 15;
    int b = blockIdx.z;
    int m0 = blockIdx.y * 64, c0 = blockIdx.x * 64;
    u64t acc[4][2] = {};
    for (int ik = 0; ik < HW; ik += 16) {
        {
            int mm = tid >> 2, k4 = (tid & 3) * 4;
            const float* krow = g_k + ((size_t)b*MI + m0 + mm)*HW + ik + k4;
            float4 k4v = *(const float4*)krow;
            const float* dv = g_dinv + b*HW + ik + k4;
            As[k4+0][mm] = k4v.x * dv[0];
            As[k4+1][mm] = k4v.y * dv[1];
            As[k4+2][mm] = k4v.z * dv[2];
            As[k4+3][mm] = k4v.w * dv[3];
        }
        #pragma unroll
        for (int r = 0; r < 4; r++) {
            int idx = tid + 256 * r;
            int kk = idx >> 6, nn = idx & 63;
            Bs[kk][nn] = g_ft[((size_t)b*HW + ik + kk)*CQ + c0 + nn];
        }
        __syncthreads();
        mm16(As, Bs, ty, tx, acc);
        __syncthreads();
    }
    #pragma unroll
    for (int u = 0; u < 4; u++) {
        int m = m0 + ty*4 + u;
        float cwm = g_cw[b*MI + m];
        float v[4];
        upk2(acc[u][0], v[0], v[1]); upk2(acc[u][1], v[2], v[3]);
        float* op = &g_z[((size_t)b*MI + m)*CQ + c0 + tx*4];
        *(float4*)op = make_float4(v[0]*cwm, v[1]*cwm, v[2]*cwm, v[3]*cwm);
    }
}

// ------------- LX[i,c] = ft[i,c] - d[i]*sum_m k[m,i]*Z[m,c] ----------------------
__global__ void __launch_bounds__(256) k_lx() {
    __shared__ __align__(16) float As[16][64];
    __shared__ __align__(16) float Bs[16][64];
    int tid = threadIdx.x;
    int ty = tid >> 4, tx = tid & 15;
    int b = blockIdx.z;
    int i0 = blockIdx.y * 64, c0 = blockIdx.x * 64;
    u64t acc[4][2] = {};
    for (int mk = 0; mk < MI; mk += 16) {
        #pragma unroll
        for (int r = 0; r < 4; r++) {
            int idx = tid + 256 * r;
            int kk = idx >> 6, col = idx & 63;
            As[kk][col] = g_k[((size_t)b*MI + mk + kk)*HW + i0 + col];
            Bs[kk][col] = g_z[((size_t)b*MI + mk + kk)*CQ + c0 + col];
        }
        __syncthreads();
        mm16(As, Bs, ty, tx, acc);
        __syncthreads();
    }
    #pragma unroll
    for (int u = 0; u < 4; u++) {
        int i = i0 + ty*4 + u;
        float di = g_dinv[b*HW + i];
        float v[4];
        upk2(acc[u][0], v[0], v[1]); upk2(acc[u][1], v[2], v[3]);
        size_t oi = ((size_t)b*HW + i)*CQ + c0 + tx*4;
        float4 f4 = *(const float4*)&g_ft[oi];
        *(float4*)&g_lx[oi] = make_float4(f4.x - di*v[0], f4.y - di*v[1],
                                          f4.z - di*v[2], f4.w - di*v[3]);
    }
}

// ------------- Y = ft + LX @ gcn_w ; store transposed into x123 ------------------
__global__ void __launch_bounds__(256) k_y(const float* __restrict__ gcn, int soff) {
    __shared__ __align__(16) float As[16][64];
    __shared__ __align__(16) float Bs[16][64];
    int tid = threadIdx.x;
    int ty = tid >> 4, tx = tid & 15;
    int b = blockIdx.z;
    int i0 = blockIdx.y * 64, c0 = blockIdx.x * 64;
    u64t acc[4][2] = {};
    for (int ck = 0; ck < CQ; ck += 16) {
        {
            int mm = tid >> 2, k4 = (tid & 3) * 4;
            float4 a4 = *(const float4*)&g_lx[((size_t)b*HW + i0 + mm)*CQ + ck + k4];
            As[k4+0][mm] = a4.x; As[k4+1][mm] = a4.y;
            As[k4+2][mm] = a4.z; As[k4+3][mm] = a4.w;
        }
        #pragma unroll
        for (int r = 0; r < 4; r++) {
            int idx = tid + 256 * r;
            int kk = idx >> 6, nn = idx & 63;
            Bs[kk][nn] = gcn[(size_t)(ck + kk)*CQ + c0 + nn];
        }
        __syncthreads();
        mm16(As, Bs, ty, tx, acc);
        __syncthreads();
    }
    #pragma unroll
    for (int u = 0; u < 4; u++) {
        int i = i0 + ty*4 + u;
        float v[4];
        upk2(acc[u][0], v[0], v[1]); upk2(acc[u][1], v[2], v[3]);
        #pragma unroll
        for (int q = 0; q < 4; q++) {
            int c = c0 + tx*4 + q;
            float val = g_ft[((size_t)b*HW + i)*CQ + c] + v[q];
            g_x123[((size_t)b*(3*CQ) + soff + c)*HW + i] = val;
        }
    }
}

// ---------------------------------------------------------------------------------
extern "C" void kernel_launch(void* const* d_in, const int* in_sizes, int n_in,
                              void* d_out, int out_size) {
    (void)in_sizes; (void)n_in; (void)out_size;
    const float* x_cur  = (const float*)d_in[0];
    const float* x_lat  = (const float*)d_in[1];
    const float* conv_w = (const float*)d_in[2];
    const float* conv_b = (const float*)d_in[3];
    const float* conv1_w= (const float*)d_in[4];
    const float* conv1_b= (const float*)d_in[5];
    const float* conv3_w= (const float*)d_in[6];
    const float* conv3_b= (const float*)d_in[7];
    const float* rw[3]  = {(const float*)d_in[8], (const float*)d_in[10], (const float*)d_in[12]};
    const float* rb[3]  = {(const float*)d_in[9], (const float*)d_in[11], (const float*)d_in[13]};
    const float* ck_w   = (const float*)d_in[14];
    const float* ck_b   = (const float*)d_in[15];
    const float* avg_w  = (const float*)d_in[16];
    const float* max_w  = (const float*)d_in[17];
    const float* gcn_w  = (const float*)d_in[18];
    float* out = (float*)d_out;

    float *p_xsum, *p_feat, *p_f, *p_k, *p_x123;
    cudaGetSymbolAddress((void**)&p_xsum, g_xsum);
    cudaGetSymbolAddress((void**)&p_feat, g_feat);
    cudaGetSymbolAddress((void**)&p_f,    g_f);
    cudaGetSymbolAddress((void**)&p_k,    g_k);
    cudaGetSymbolAddress((void**)&p_x123, g_x123);

    cudaFuncSetAttribute(k_conv_mma, cudaFuncAttributeMaxDynamicSharedMemorySize, SMEM_CONV);

    k_upsample_fuse<<<(BB*CC*HW + 255)/256, 256>>>(x_cur, x_lat);

    const int dils[3] = {1, 2, 4};
    for (int s = 0; s < 3; s++) {
        const float* cin = (s == 0) ? p_xsum : p_feat;
        k_fuse_weights2<<<(9*CQ*CC + 255)/256, 256>>>(rw[s], rb[s], conv_w, conv_b);
        k_split_in<<<dim3(CC/32, HW/32, BB), dim3(32, 8)>>>(cin);
        k_conv_mma<<<dim3(128, 2), 256, SMEM_CONV>>>(dils[s]);

        // graph reasoning on g_f -> x_{s+1}
        k_avgmax<<<2048, 256>>>();
        k_cw<<<BB, 128>>>(avg_w, max_w);
        k_gemm<<<dim3(256, 2), 256>>>(p_f, ck_w, ck_b, nullptr, p_k, CQ, MI, 1);
        k_zero_rs<<<(BB*HW + 255)/256, 256>>>();
        k_Arowsum<<<dim3(4, 4, BB), 256>>>();
        k_dinv<<<(BB*HW + 255)/256, 256>>>();
        k_transpose<<<dim3(8, 8, BB), dim3(32, 8)>>>();
        k_ptz<<<dim3(4, 2, BB), 256>>>();
        k_lx<<<dim3(4, 4, BB), 256>>>();
        k_y<<<dim3(4, 4, BB), 256>>>(gcn_w, s * CQ);

        if (s < 2)  // feature = conv1x1(f) + x_sum
            k_gemm<<<dim3(256, 16), 256>>>(p_f, conv1_w, conv1_b, p_xsum, p_feat, CQ, CC, 0);
    }

    // final: out = conv3_w @ concat(x1,x2,x3) + conv3_b
    k_gemm<<<dim3(256, 16), 256>>>(p_x123, conv3_w, conv3_b, nullptr, out, 3*CQ, CC, 0);
}

// round 8
// speedup vs baseline: 2.8906x; 1.0441x over previous
#include <cuda_runtime.h>
#include <cuda_bf16.h>
#include <math.h>
#include <stdint.h>

#define BB 64
#define CC 1024
#define CQ 256
#define MI 128
#define HW 256

// ---------------- scratch (device globals; no allocation allowed) ----------------
__device__ __align__(256) float g_xsum[BB*CC*HW];    // x_sum
__device__ __align__(256) float g_feat[BB*CC*HW];    // feature (stage 2/3 input)
__device__ __align__(256) float g_f   [BB*CQ*HW];    // current f_i  [b][c][hw]
__device__ __align__(256) float g_ft  [BB*HW*CQ];    // f transposed [b][i][c]
__device__ __align__(256) float g_bf  [CQ];
__device__ __align__(256) float g_k   [BB*MI*HW];    // relu(k) [b][m][i]
__device__ __align__(256) float g_cw  [BB*MI];
__device__ __align__(256) float g_scw [BB*MI];       // sqrt(cw)
__device__ __align__(256) float g_avg [BB*CQ];
__device__ __align__(256) float g_mx  [BB*CQ];
__device__ __align__(256) float g_rs  [BB*HW];       // row sums of sigmoid(A)
__device__ __align__(256) float g_dinv[BB*HW];       // rs^-0.5
__device__ __align__(256) float g_z   [BB*MI*CQ];    // cw ⊙ PtX
__device__ __align__(256) float g_lx  [BB*HW*CQ];    // LX [b][i][c]
__device__ __align__(256) float g_x123[BB*3*CQ*HW];  // concat(x1,x2,x3) [b][c][hw]
// bf16 hi/lo splits for the tensor-core conv
__device__ __align__(256) __nv_bfloat16 g_wh [9*CQ*CC];   // weights [t][o][c]
__device__ __align__(256) __nv_bfloat16 g_wl [9*CQ*CC];
__device__ __align__(256) __nv_bfloat16 g_inh[BB*HW*CC];  // input  [b][hw][c]
__device__ __align__(256) __nv_bfloat16 g_inl[BB*HW*CC];

// ---------------- packed fp32x2 helpers (FFMA2 path) -----------------------------
typedef unsigned long long u64t;
__device__ __forceinline__ u64t pk2(float a, float b) {
    u64t r; asm("mov.b64 %0, {%1,%2};" : "=l"(r) : "f"(a), "f"(b)); return r;
}
__device__ __forceinline__ void upk2(u64t v, float& a, float& b) {
    asm("mov.b64 {%0,%1}, %2;" : "=f"(a), "=f"(b) : "l"(v));
}
__device__ __forceinline__ u64t fma2(u64t a, u64t b, u64t c) {
    u64t d; asm("fma.rn.f32x2 %0, %1, %2, %3;" : "=l"(d) : "l"(a), "l"(b), "l"(c)); return d;
}

__device__ __forceinline__ void mm16(const float (*__restrict__ Ws)[64],
                                     const float (*__restrict__ Is)[64],
                                     int ty, int tx, u64t acc[4][2]) {
    #pragma unroll
    for (int kk = 0; kk < 16; kk++) {
        float4 a4 = *(const float4*)&Ws[kk][ty*4];
        float4 b4 = *(const float4*)&Is[kk][tx*4];
        u64t b01 = pk2(b4.x, b4.y);
        u64t b23 = pk2(b4.z, b4.w);
        u64t ad;
        ad = pk2(a4.x, a4.x); acc[0][0] = fma2(ad, b01, acc[0][0]); acc[0][1] = fma2(ad, b23, acc[0][1]);
        ad = pk2(a4.y, a4.y); acc[1][0] = fma2(ad, b01, acc[1][0]); acc[1][1] = fma2(ad, b23, acc[1][1]);
        ad = pk2(a4.z, a4.z); acc[2][0] = fma2(ad, b01, acc[2][0]); acc[2][1] = fma2(ad, b23, acc[2][1]);
        ad = pk2(a4.w, a4.w); acc[3][0] = fma2(ad, b01, acc[3][0]); acc[3][1] = fma2(ad, b23, acc[3][1]);
    }
}

// ---------------- bf16 mma.sync / ldmatrix / cp.async helpers --------------------
__device__ __forceinline__ void mma16816(float d[4], const uint32_t a[4], const uint32_t b0, const uint32_t b1) {
    asm volatile("mma.sync.aligned.m16n8k16.row.col.f32.bf16.bf16.f32 "
        "{%0,%1,%2,%3}, {%4,%5,%6,%7}, {%8,%9}, {%0,%1,%2,%3};"
        : "+f"(d[0]), "+f"(d[1]), "+f"(d[2]), "+f"(d[3])
        : "r"(a[0]), "r"(a[1]), "r"(a[2]), "r"(a[3]), "r"(b0), "r"(b1));
}
__device__ __forceinline__ void ldsm4(uint32_t r[4], uint32_t addr) {
    asm volatile("ldmatrix.sync.aligned.m8n8.x4.shared.b16 {%0,%1,%2,%3}, [%4];"
        : "=r"(r[0]), "=r"(r[1]), "=r"(r[2]), "=r"(r[3]) : "r"(addr));
}
__device__ __forceinline__ uint32_t smem_u32(const void* p) {
    uint32_t a;
    asm("{ .reg .u64 t; cvta.to.shared.u64 t, %1; cvt.u32.u64 %0, t; }" : "=r"(a) : "l"(p));
    return a;
}
__device__ __forceinline__ void cp16(uint32_t dst, const void* src, int sz) {
    asm volatile("cp.async.cg.shared.global [%0], [%1], 16, %2;"
                 :: "r"(dst), "l"(src), "r"(sz) : "memory");
}
__device__ __forceinline__ void cp_commit() {
    asm volatile("cp.async.commit_group;" ::: "memory");
}
__device__ __forceinline__ void cp_wait1() {
    asm volatile("cp.async.wait_group 1;" ::: "memory");
}
__device__ __forceinline__ void cp_wait0() {
    asm volatile("cp.async.wait_group 0;" ::: "memory");
}

// ------------- tensor-core dilated conv3x3 (fused 1x1), bf16x3 split -------------
// grid (128, 2): bx -> (b = bx>>1, hw0 = (bx&1)*128); by -> m0 = by*128
// smem: double-buffered AH/AL/BH/BL tiles, 128 rows x 32 k bf16, row pitch 80B
#define CPITCH 80           // bytes per smem row (64B data + 16B pad -> conflict-free)
#define ABYTES (128*CPITCH) // 10240 per array
#define STAGEB (4*ABYTES)   // 40960 per pipeline stage
#define SMEM_CONV (2*STAGEB)

__device__ __forceinline__ void conv_stage(int tid, int m0, int hw0, int bb, int ch, int dil,
                                           uint32_t sAH, uint32_t sAL, uint32_t sBH, uint32_t sBL) {
    int t  = ch >> 5;
    int ck = (ch & 31) << 5;
    int dy = dil * ((t / 3) - 1);
    int dx = dil * ((t % 3) - 1);
    const char* wh = (const char*)g_wh;
    const char* wl = (const char*)g_wl;
    const char* ih = (const char*)g_inh;
    const char* il = (const char*)g_inl;
    #pragma unroll
    for (int i = 0; i < 2; i++) {
        int cid = tid + 256*i;          // 0..511
        int row = cid >> 2;             // 0..127
        int seg = (cid & 3) * 16;       // byte offset within 64B row
        size_t woff = (((size_t)(t*CQ + m0 + row))*CC + ck)*2 + seg;
        cp16(sAH + row*CPITCH + seg, wh + woff, 16);
        cp16(sAL + row*CPITCH + seg, wl + woff, 16);
        int hw = hw0 + row;
        int y = (hw >> 4) + dy, x = (hw & 15) + dx;
        int ok = ((unsigned)y < 16u) && ((unsigned)x < 16u);
        int ridx = ok ? (y*16 + x) : 0;
        int sz = ok ? 16 : 0;
        size_t ioff = (((size_t)(bb*HW + ridx))*CC + ck)*2 + seg;
        cp16(sBH + row*CPITCH + seg, ih + ioff, sz);
        cp16(sBL + row*CPITCH + seg, il + ioff, sz);
    }
}

__global__ void __launch_bounds__(256) k_conv_mma(int dil) {
    extern __shared__ char smem[];
    uint32_t sb = smem_u32(smem);
    int tid = threadIdx.x;
    int wid = tid >> 5, lane = tid & 31;
    int gid = lane >> 2, q = lane & 3;
    int warp_m = wid >> 2, warp_n = wid & 3;
    int bb  = blockIdx.x >> 1;
    int hw0 = (blockIdx.x & 1) * 128;
    int m0  = blockIdx.y * 128;

    float acc[4][4][4];
    #pragma unroll
    for (int mt = 0; mt < 4; mt++)
        #pragma unroll
        for (int nt = 0; nt < 4; nt++)
            #pragma unroll
            for (int e = 0; e < 4; e++) acc[mt][nt][e] = 0.f;

    // lane-constant ldmatrix base offsets (within an array)
    // A x4: matrices {m0-7.k0, m8-15.k0, m0-7.k8, m8-15.k8}
    uint32_t aoffA = (uint32_t)((warp_m*64 + (lane & 7) + ((lane >> 3) & 1)*8) * CPITCH
                                + (lane >> 4) * 16);
    // B x4: matrices {nt.k0, nt.k8, nt+1.k0, nt+1.k8}
    uint32_t aoffB = (uint32_t)((warp_n*32 + ((lane >> 4) & 1)*8 + (lane & 7)) * CPITCH
                                + ((lane >> 3) & 1) * 16);

    const int NCH = 9 * 32;   // 288 chunks of K=32
    conv_stage(tid, m0, hw0, bb, 0, dil, sb, sb + ABYTES, sb + 2*ABYTES, sb + 3*ABYTES);
    cp_commit();

    for (int ch = 0; ch < NCH; ch++) {
        __syncthreads();            // all warps done reading buf (ch+1)&1 from mma(ch-1)
        if (ch + 1 < NCH) {
            uint32_t bs = sb + ((ch + 1) & 1) * STAGEB;
            conv_stage(tid, m0, hw0, bb, ch + 1, dil, bs, bs + ABYTES, bs + 2*ABYTES, bs + 3*ABYTES);
            cp_commit();
            cp_wait1();             // group ch complete (group ch+1 may be in flight)
        } else {
            cp_wait0();
        }
        __syncthreads();            // copies visible to all warps

        uint32_t bufb = sb + (ch & 1) * STAGEB;
        uint32_t aAH = bufb + aoffA;
        uint32_t aAL = bufb + ABYTES + aoffA;
        uint32_t aBH = bufb + 2*ABYTES + aoffB;
        uint32_t aBL = bufb + 3*ABYTES + aoffB;

        #pragma unroll
        for (int s = 0; s < 2; s++) {
            uint32_t so = s * 32;
            uint32_t afh[4][4], afl[4][4];
            #pragma unroll
            for (int mt = 0; mt < 4; mt++) {
                ldsm4(afh[mt], aAH + mt*(16*CPITCH) + so);
                ldsm4(afl[mt], aAL + mt*(16*CPITCH) + so);
            }
            uint32_t bh[2][4], bl[2][4];
            #pragma unroll
            for (int p = 0; p < 2; p++) {
                ldsm4(bh[p], aBH + p*(16*CPITCH) + so);
                ldsm4(bl[p], aBL + p*(16*CPITCH) + so);
            }
            #pragma unroll
            for (int mt = 0; mt < 4; mt++)
                #pragma unroll
                for (int nt = 0; nt < 4; nt++) {
                    uint32_t b0h = bh[nt >> 1][(nt & 1)*2], b1h = bh[nt >> 1][(nt & 1)*2 + 1];
                    uint32_t b0l = bl[nt >> 1][(nt & 1)*2], b1l = bl[nt >> 1][(nt & 1)*2 + 1];
                    mma16816(acc[mt][nt], afh[mt], b0h, b1h);
                    mma16816(acc[mt][nt], afh[mt], b0l, b1l);
                    mma16816(acc[mt][nt], afl[mt], b0h, b1h);
                }
        }
    }

    // ---- epilogue: D[gid][2q,2q+1] & D[gid+8][...] per tile, + bias ----
    #pragma unroll
    for (int mt = 0; mt < 4; mt++) {
        int oc = m0 + warp_m*64 + mt*16 + gid;
        float bi0 = g_bf[oc], bi1 = g_bf[oc + 8];
        #pragma unroll
        for (int nt = 0; nt < 4; nt++) {
            int hw = hw0 + warp_n*32 + nt*8 + 2*q;
            float2 v0 = make_float2(acc[mt][nt][0] + bi0, acc[mt][nt][1] + bi0);
            *(float2*)&g_f[((size_t)bb*CQ + oc)*HW + hw] = v0;
            float2 v1 = make_float2(acc[mt][nt][2] + bi1, acc[mt][nt][3] + bi1);
            *(float2*)&g_f[((size_t)bb*CQ + oc + 8)*HW + hw] = v1;
        }
    }
}

// ------------- fused weights -> bf16 hi/lo, transposed [t][o][c]; bias -----------
__global__ void k_fuse_weights2(const float* __restrict__ rw, const float* __restrict__ rb,
                                const float* __restrict__ cw, const float* __restrict__ cb) {
    int idx = blockIdx.x * 256 + threadIdx.x;   // over 9*256*1024, layout ((t*CQ+o)*CC+c)
    if (idx >= 9*CQ*CC) return;
    int c = idx & 1023;
    int to = idx >> 10;
    int o = to & 255;
    int t = to >> 8;
    float v = rw[((size_t)o*CC + c)*9 + t];
    if (t == 4) v += cw[(size_t)o*CC + c];
    __nv_bfloat16 vh = __float2bfloat16(v);
    g_wh[idx] = vh;
    g_wl[idx] = __float2bfloat16(v - __bfloat162float(vh));
    if (idx < CQ) g_bf[idx] = rb[idx] + cb[idx];
}

// ------------- split conv input into bf16 hi/lo, transposed [b][hw][c] -----------
__global__ void k_split_in(const float* __restrict__ in) {
    __shared__ float t32[32][33];
    int b = blockIdx.z;
    int c0 = blockIdx.x * 32, hw0 = blockIdx.y * 32;
    for (int j = threadIdx.y; j < 32; j += 8)
        t32[j][threadIdx.x] = in[((size_t)b*CC + c0 + j)*HW + hw0 + threadIdx.x];
    __syncthreads();
    for (int j = threadIdx.y; j < 32; j += 8) {
        float v = t32[threadIdx.x][j];
        __nv_bfloat16 vh = __float2bfloat16(v);
        size_t oi = ((size_t)b*HW + hw0 + j)*CC + c0 + threadIdx.x;
        g_inh[oi] = vh;
        g_inl[oi] = __float2bfloat16(v - __bfloat162float(vh));
    }
}

// ------------- generic 1x1 GEMM over NCHW: out = [relu](W @ in + bias [+ add]) ---
__global__ void __launch_bounds__(256) k_gemm(const float* __restrict__ in, const float* __restrict__ Wt,
                       const float* __restrict__ bias, const float* __restrict__ add,
                       float* __restrict__ out, int Ci, int Co, int relu) {
    __shared__ __align__(16) float Ws[16][64];
    __shared__ __align__(16) float Is[16][64];
    int tid = threadIdx.x;
    int ty = tid >> 4, tx = tid & 15;
    int n0 = blockIdx.x * 64;
    int b = n0 >> 8, hw0 = n0 & 255;
    int m0 = blockIdx.y * 64;
    u64t acc[4][2] = {};
    const float* inb = in + (size_t)b * Ci * HW;
    for (int ck = 0; ck < Ci; ck += 16) {
        {
            int mm = tid >> 2, k4 = (tid & 3) * 4;
            float4 w4 = *(const float4*)&Wt[(size_t)(m0 + mm)*Ci + ck + k4];
            Ws[k4+0][mm] = w4.x; Ws[k4+1][mm] = w4.y;
            Ws[k4+2][mm] = w4.z; Ws[k4+3][mm] = w4.w;
        }
        #pragma unroll
        for (int r = 0; r < 4; r++) {
            int idx = tid + 256 * r;
            int kk = idx >> 6, nn = idx & 63;
            Is[kk][nn] = inb[(size_t)(ck + kk)*HW + hw0 + nn];
        }
        __syncthreads();
        mm16(Ws, Is, ty, tx, acc);
        __syncthreads();
    }
    #pragma unroll
    for (int u = 0; u < 4; u++) {
        int o = m0 + ty*4 + u;
        float bi = bias[o];
        float v[4];
        upk2(acc[u][0], v[0], v[1]); upk2(acc[u][1], v[2], v[3]);
        size_t ob = ((size_t)b*Co + o)*HW + hw0 + tx*4;
        #pragma unroll
        for (int q = 0; q < 4; q++) {
            float vv = v[q] + bi;
            if (relu) vv = fmaxf(vv, 0.f);
            if (add) vv += add[ob + q];
            out[ob + q] = vv;
        }
    }
}

// ---------------- upsample (align_corners) + fuse: x_sum = x_cur*(up+1) ----------
__global__ void k_upsample_fuse(const float* __restrict__ xc, const float* __restrict__ xl) {
    int idx = blockIdx.x * 256 + threadIdx.x;
    if (idx >= BB*CC*HW) return;
    int hw = idx & 255; int bc = idx >> 8;
    int y = hw >> 4, x = hw & 15;
    float ys = y * (7.0f / 15.0f);
    float xs = x * (7.0f / 15.0f);
    int y0 = (int)floorf(ys), x0 = (int)floorf(xs);
    int y1 = min(y0 + 1, 7), x1 = min(x0 + 1, 7);
    float wy = ys - (float)y0, wx = xs - (float)x0;
    const float* base = xl + (size_t)bc * 64;
    float v00 = base[y0*8+x0], v01 = base[y0*8+x1];
    float v10 = base[y1*8+x0], v11 = base[y1*8+x1];
    float top = v00*(1.f-wx) + v01*wx;
    float bot = v10*(1.f-wx) + v11*wx;
    float up  = top*(1.f-wy) + bot*wy;
    g_xsum[idx] = xc[idx] * (up + 1.0f);
}

// ------------- per-(b,c) spatial mean/max over HW=256 (one warp each) ------------
__global__ void k_avgmax() {
    int gw = (blockIdx.x * blockDim.x + threadIdx.x) >> 5;
    int lane = threadIdx.x & 31;
    if (gw >= BB*CQ) return;
    const float* p = g_f + (size_t)gw * HW;
    float s = 0.f, m = -INFINITY;
    for (int i = lane; i < HW; i += 32) { float v = p[i]; s += v; m = fmaxf(m, v); }
    #pragma unroll
    for (int off = 16; off; off >>= 1) {
        s += __shfl_down_sync(0xffffffffu, s, off);
        m  = fmaxf(m, __shfl_down_sync(0xffffffffu, m, off));
    }
    if (lane == 0) { g_avg[gw] = s * (1.0f/256.0f); g_mx[gw] = m; }
}

// ------------- cw = sigmoid(relu(avg@avg_w^T) + relu(mx@max_w^T)) ----------------
__global__ void k_cw(const float* __restrict__ aw, const float* __restrict__ mw) {
    __shared__ float sa[CQ], sm[CQ];
    int b = blockIdx.x, m = threadIdx.x;
    for (int i = m; i < CQ; i += 128) {
        sa[i] = g_avg[b*CQ + i];
        sm[i] = g_mx [b*CQ + i];
    }
    __syncthreads();
    float s1 = 0.f, s2 = 0.f;
    for (int c = 0; c < CQ; c++) {
        s1 += sa[c] * aw[m*CQ + c];
        s2 += sm[c] * mw[m*CQ + c];
    }
    float val = fmaxf(s1, 0.f) + fmaxf(s2, 0.f);
    float cwv = 1.0f / (1.0f + expf(-val));
    g_cw [b*MI + m] = cwv;
    g_scw[b*MI + m] = sqrtf(cwv);
}

__global__ void k_zero_rs() {
    int idx = blockIdx.x * 256 + threadIdx.x;
    if (idx < BB*HW) g_rs[idx] = 0.f;
}

// ------------- row-sums of sigmoid(G^T G), G[m,i] = sqrt(cw[m])*k[m,i] -----------
__global__ void __launch_bounds__(256) k_Arowsum() {
    __shared__ __align__(16) float Gi[16][64];
    __shared__ __align__(16) float Gj[16][64];
    __shared__ float rsum[64];
    int tid = threadIdx.x;
    int ty = tid >> 4, tx = tid & 15;
    int b = blockIdx.z;
    int i0 = blockIdx.y * 64, j0 = blockIdx.x * 64;
    if (tid < 64) rsum[tid] = 0.f;
    u64t acc[4][2] = {};
    for (int mk = 0; mk < MI; mk += 16) {
        #pragma unroll
        for (int r = 0; r < 4; r++) {
            int idx = tid + 256 * r;
            int kk = idx >> 6, col = idx & 63;
            float sc = g_scw[b*MI + mk + kk];
            const float* krow = g_k + ((size_t)b*MI + mk + kk)*HW;
            Gi[kk][col] = krow[i0 + col] * sc;
            Gj[kk][col] = krow[j0 + col] * sc;
        }
        __syncthreads();
        mm16(Gi, Gj, ty, tx, acc);
        __syncthreads();
    }
    #pragma unroll
    for (int u = 0; u < 4; u++) {
        float v[4];
        upk2(acc[u][0], v[0], v[1]); upk2(acc[u][1], v[2], v[3]);
        float part = 0.f;
        #pragma unroll
        for (int q = 0; q < 4; q++)
            part += 1.0f / (1.0f + expf(-v[q]));
        atomicAdd(&rsum[ty*4 + u], part);
    }
    __syncthreads();
    if (tid < 64) atomicAdd(&g_rs[b*HW + i0 + tid], rsum[tid]);
}

__global__ void k_dinv() {
    int idx = blockIdx.x * 256 + threadIdx.x;
    if (idx < BB*HW) g_dinv[idx] = rsqrtf(g_rs[idx]);
}

// ------------- transpose f[b][c][i] -> ft[b][i][c] -------------------------------
__global__ void k_transpose() {
    __shared__ float t[32][33];
    int b = blockIdx.z;
    int c0 = blockIdx.x * 32, i0 = blockIdx.y * 32;
    for (int j = threadIdx.y; j < 32; j += 8)
        t[j][threadIdx.x] = g_f[((size_t)b*CQ + c0 + j)*HW + i0 + threadIdx.x];
    __syncthreads();
    for (int j = threadIdx.y; j < 32; j += 8)
        g_ft[((size_t)b*HW + i0 + j)*CQ + c0 + threadIdx.x] = t[threadIdx.x][j];
}

// ------------- Z[m,c] = cw[m] * sum_i d[i]*k[m,i]*ft[i,c] ------------------------
__global__ void __launch_bounds__(256) k_ptz() {
    __shared__ __align__(16) float As[16][64];
    __shared__ __align__(16) float Bs[16][64];
    int tid = threadIdx.x;
    int ty = tid >> 4, tx = tid & 15;
    int b = blockIdx.z;
    int m0 = blockIdx.y * 64, c0 = blockIdx.x * 64;
    u64t acc[4][2] = {};
    for (int ik = 0; ik < HW; ik += 16) {
        {
            int mm = tid >> 2, k4 = (tid & 3) * 4;
            const float* krow = g_k + ((size_t)b*MI + m0 + mm)*HW + ik + k4;
            float4 k4v = *(const float4*)krow;
            const float* dv = g_dinv + b*HW + ik + k4;
            As[k4+0][mm] = k4v.x * dv[0];
            As[k4+1][mm] = k4v.y * dv[1];
            As[k4+2][mm] = k4v.z * dv[2];
            As[k4+3][mm] = k4v.w * dv[3];
        }
        #pragma unroll
        for (int r = 0; r < 4; r++) {
            int idx = tid + 256 * r;
            int kk = idx >> 6, nn = idx & 63;
            Bs[kk][nn] = g_ft[((size_t)b*HW + ik + kk)*CQ + c0 + nn];
        }
        __syncthreads();
        mm16(As, Bs, ty, tx, acc);
        __syncthreads();
    }
    #pragma unroll
    for (int u = 0; u < 4; u++) {
        int m = m0 + ty*4 + u;
        float cwm = g_cw[b*MI + m];
        float v[4];
        upk2(acc[u][0], v[0], v[1]); upk2(acc[u][1], v[2], v[3]);
        float* op = &g_z[((size_t)b*MI + m)*CQ + c0 + tx*4];
        *(float4*)op = make_float4(v[0]*cwm, v[1]*cwm, v[2]*cwm, v[3]*cwm);
    }
}

// ------------- LX[i,c] = ft[i,c] - d[i]*sum_m k[m,i]*Z[m,c] ----------------------
__global__ void __launch_bounds__(256) k_lx() {
    __shared__ __align__(16) float As[16][64];
    __shared__ __align__(16) float Bs[16][64];
    int tid = threadIdx.x;
    int ty = tid >> 4, tx = tid & 15;
    int b = blockIdx.z;
    int i0 = blockIdx.y * 64, c0 = blockIdx.x * 64;
    u64t acc[4][2] = {};
    for (int mk = 0; mk < MI; mk += 16) {
        #pragma unroll
        for (int r = 0; r < 4; r++) {
            int idx = tid + 256 * r;
            int kk = idx >> 6, col = idx & 63;
            As[kk][col] = g_k[((size_t)b*MI + mk + kk)*HW + i0 + col];
            Bs[kk][col] = g_z[((size_t)b*MI + mk + kk)*CQ + c0 + col];
        }
        __syncthreads();
        mm16(As, Bs, ty, tx, acc);
        __syncthreads();
    }
    #pragma unroll
    for (int u = 0; u < 4; u++) {
        int i = i0 + ty*4 + u;
        float di = g_dinv[b*HW + i];
        float v[4];
        upk2(acc[u][0], v[0], v[1]); upk2(acc[u][1], v[2], v[3]);
        size_t oi = ((size_t)b*HW + i)*CQ + c0 + tx*4;
        float4 f4 = *(const float4*)&g_ft[oi];
        *(float4*)&g_lx[oi] = make_float4(f4.x - di*v[0], f4.y - di*v[1],
                                          f4.z - di*v[2], f4.w - di*v[3]);
    }
}

// ------------- Y = ft + LX @ gcn_w ; store transposed into x123 ------------------
__global__ void __launch_bounds__(256) k_y(const float* __restrict__ gcn, int soff) {
    __shared__ __align__(16) float As[16][64];
    __shared__ __align__(16) float Bs[16][64];
    int tid = threadIdx.x;
    int ty = tid >> 4, tx = tid & 15;
    int b = blockIdx.z;
    int i0 = blockIdx.y * 64, c0 = blockIdx.x * 64;
    u64t acc[4][2] = {};
    for (int ck = 0; ck < CQ; ck += 16) {
        {
            int mm = tid >> 2, k4 = (tid & 3) * 4;
            float4 a4 = *(const float4*)&g_lx[((size_t)b*HW + i0 + mm)*CQ + ck + k4];
            As[k4+0][mm] = a4.x; As[k4+1][mm] = a4.y;
            As[k4+2][mm] = a4.z; As[k4+3][mm] = a4.w;
        }
        #pragma unroll
        for (int r = 0; r < 4; r++) {
            int idx = tid + 256 * r;
            int kk = idx >> 6, nn = idx & 63;
            Bs[kk][nn] = gcn[(size_t)(ck + kk)*CQ + c0 + nn];
        }
        __syncthreads();
        mm16(As, Bs, ty, tx, acc);
        __syncthreads();
    }
    #pragma unroll
    for (int u = 0; u < 4; u++) {
        int i = i0 + ty*4 + u;
        float v[4];
        upk2(acc[u][0], v[0], v[1]); upk2(acc[u][1], v[2], v[3]);
        #pragma unroll
        for (int q = 0; q < 4; q++) {
            int c = c0 + tx*4 + q;
            float val = g_ft[((size_t)b*HW + i)*CQ + c] + v[q];
            g_x123[((size_t)b*(3*CQ) + soff + c)*HW + i] = val;
        }
    }
}

// ---------------------------------------------------------------------------------
extern "C" void kernel_launch(void* const* d_in, const int* in_sizes, int n_in,
                              void* d_out, int out_size) {
    (void)in_sizes; (void)n_in; (void)out_size;
    const float* x_cur  = (const float*)d_in[0];
    const float* x_lat  = (const float*)d_in[1];
    const float* conv_w = (const float*)d_in[2];
    const float* conv_b = (const float*)d_in[3];
    const float* conv1_w= (const float*)d_in[4];
    const float* conv1_b= (const float*)d_in[5];
    const float* conv3_w= (const float*)d_in[6];
    const float* conv3_b= (const float*)d_in[7];
    const float* rw[3]  = {(const float*)d_in[8], (const float*)d_in[10], (const float*)d_in[12]};
    const float* rb[3]  = {(const float*)d_in[9], (const float*)d_in[11], (const float*)d_in[13]};
    const float* ck_w   = (const float*)d_in[14];
    const float* ck_b   = (const float*)d_in[15];
    const float* avg_w  = (const float*)d_in[16];
    const float* max_w  = (const float*)d_in[17];
    const float* gcn_w  = (const float*)d_in[18];
    float* out = (float*)d_out;

    float *p_xsum, *p_feat, *p_f, *p_k, *p_x123;
    cudaGetSymbolAddress((void**)&p_xsum, g_xsum);
    cudaGetSymbolAddress((void**)&p_feat, g_feat);
    cudaGetSymbolAddress((void**)&p_f,    g_f);
    cudaGetSymbolAddress((void**)&p_k,    g_k);
    cudaGetSymbolAddress((void**)&p_x123, g_x123);

    cudaFuncSetAttribute(k_conv_mma, cudaFuncAttributeMaxDynamicSharedMemorySize, SMEM_CONV);

    k_upsample_fuse<<<(BB*CC*HW + 255)/256, 256>>>(x_cur, x_lat);

    const int dils[3] = {1, 2, 4};
    for (int s = 0; s < 3; s++) {
        const float* cin = (s == 0) ? p_xsum : p_feat;
        k_fuse_weights2<<<(9*CQ*CC + 255)/256, 256>>>(rw[s], rb[s], conv_w, conv_b);
        k_split_in<<<dim3(CC/32, HW/32, BB), dim3(32, 8)>>>(cin);
        k_conv_mma<<<dim3(128, 2), 256, SMEM_CONV>>>(dils[s]);

        // graph reasoning on g_f -> x_{s+1}
        k_avgmax<<<2048, 256>>>();
        k_cw<<<BB, 128>>>(avg_w, max_w);
        k_gemm<<<dim3(256, 2), 256>>>(p_f, ck_w, ck_b, nullptr, p_k, CQ, MI, 1);
        k_zero_rs<<<(BB*HW + 255)/256, 256>>>();
        k_Arowsum<<<dim3(4, 4, BB), 256>>>();
        k_dinv<<<(BB*HW + 255)/256, 256>>>();
        k_transpose<<<dim3(8, 8, BB), dim3(32, 8)>>>();
        k_ptz<<<dim3(4, 2, BB), 256>>>();
        k_lx<<<dim3(4, 4, BB), 256>>>();
        k_y<<<dim3(4, 4, BB), 256>>>(gcn_w, s * CQ);

        if (s < 2)  // feature = conv1x1(f) + x_sum
            k_gemm<<<dim3(256, 16), 256>>>(p_f, conv1_w, conv1_b, p_xsum, p_feat, CQ, CC, 0);
    }

    // final: out = conv3_w @ concat(x1,x2,x3) + conv3_b
    k_gemm<<<dim3(256, 16), 256>>>(p_x123, conv3_w, conv3_b, nullptr, out, 3*CQ, CC, 0);
}